// round 6
// baseline (speedup 1.0000x reference)
#include <cuda_runtime.h>
#include <cuda_bf16.h>
#include <cuda_fp16.h>
#include <stdint.h>
#include <math.h>

// Problem constants
#define BB 2
#define SS 1024
#define DD 512
#define HH 8
#define LL 6
#define VV 32000
#define FFN 2048
#define NT (BB*SS)          // 2048 tokens

// ---------------------------------------------------------------------------
// Device scratch (static, no allocations)
// ---------------------------------------------------------------------------
__device__ float g_X  [NT*DD];
__device__ float g_QKV[NT*3*DD];
__device__ float g_TMP[NT*DD];
__device__ float g_HB [NT*2*FFN];

__device__ __nv_bfloat16 g_wqkv2[(size_t)LL*3*DD*2*DD];   // [rows, 2K] hi|lo
__device__ __nv_bfloat16 g_wo2  [(size_t)LL*DD*2*DD];
__device__ __nv_bfloat16 g_w12  [(size_t)LL*2*FFN*2*DD];
__device__ __nv_bfloat16 g_w22  [(size_t)LL*DD*2*FFN];
__device__ __nv_bfloat16 g_x2   [(size_t)NT*2*DD];
__device__ __nv_bfloat16 g_att2 [(size_t)NT*2*DD];
__device__ __nv_bfloat16 g_ff2  [(size_t)NT*2*FFN];
__device__ __half        g_embh [(size_t)VV*DD];          // fp16 for LM head
__device__ __half        g_lnfh [(size_t)NT*DD];

// ---------------------------------------------------------------------------
// PTX helpers (baseline ISA only: cp.async, ldmatrix, mma.sync)
// ---------------------------------------------------------------------------
__device__ __forceinline__ uint32_t smem_to_u32(const void* p) {
    uint32_t a;
    asm("{ .reg .u64 t; cvta.to.shared.u64 t, %1; cvt.u32.u64 %0, t; }"
        : "=r"(a) : "l"(p));
    return a;
}
__device__ __forceinline__ void cp16(uint32_t dst, const void* src) {
    asm volatile("cp.async.cg.shared.global [%0], [%1], 16;\n" :: "r"(dst), "l"(src) : "memory");
}
#define CP_COMMIT()  asm volatile("cp.async.commit_group;" ::: "memory")
#define CP_WAIT1()   asm volatile("cp.async.wait_group 1;" ::: "memory")

__device__ __forceinline__ void ldm_x4(uint32_t* r, uint32_t addr) {
    asm volatile("ldmatrix.sync.aligned.m8n8.x4.shared.b16 {%0,%1,%2,%3}, [%4];"
        : "=r"(r[0]), "=r"(r[1]), "=r"(r[2]), "=r"(r[3]) : "r"(addr));
}
template<bool F16>
__device__ __forceinline__ void mma16816(float* c, const uint32_t* a,
                                         uint32_t b0, uint32_t b1) {
    if (F16)
        asm volatile(
            "mma.sync.aligned.m16n8k16.row.col.f32.f16.f16.f32 "
            "{%0,%1,%2,%3}, {%4,%5,%6,%7}, {%8,%9}, {%0,%1,%2,%3};"
            : "+f"(c[0]), "+f"(c[1]), "+f"(c[2]), "+f"(c[3])
            : "r"(a[0]), "r"(a[1]), "r"(a[2]), "r"(a[3]), "r"(b0), "r"(b1));
    else
        asm volatile(
            "mma.sync.aligned.m16n8k16.row.col.f32.bf16.bf16.f32 "
            "{%0,%1,%2,%3}, {%4,%5,%6,%7}, {%8,%9}, {%0,%1,%2,%3};"
            : "+f"(c[0]), "+f"(c[1]), "+f"(c[2]), "+f"(c[3])
            : "r"(a[0]), "r"(a[1]), "r"(a[2]), "r"(a[3]), "r"(b0), "r"(b1));
}

// ---------------------------------------------------------------------------
// bf16 hi/lo split helpers
// ---------------------------------------------------------------------------
__device__ __forceinline__ void split2(float x, __nv_bfloat16* hi_p, __nv_bfloat16* lo_p) {
    __nv_bfloat16 h = __float2bfloat16_rn(x);
    *hi_p = h;
    *lo_p = __float2bfloat16_rn(x - __bfloat162float(h));
}

// Fused weight split: all 4 weight tensors in one launch.
#define RQKV (LL*3*DD)
#define RWO  (LL*DD)
#define RW1  (LL*2*FFN)
#define RW2  (LL*DD)
__global__ __launch_bounds__(256) void prep_split(
    const float* __restrict__ Wqkv, const float* __restrict__ Wo,
    const float* __restrict__ W1,   const float* __restrict__ W2,
    __nv_bfloat16* __restrict__ wqkv2, __nv_bfloat16* __restrict__ wo2,
    __nv_bfloat16* __restrict__ w12,   __nv_bfloat16* __restrict__ w22)
{
    int r = blockIdx.x;
    const float* s; __nv_bfloat16* d; int K;
    if (r < RQKV)                    { s = Wqkv + (size_t)r * DD; d = wqkv2 + (size_t)r * 2 * DD; K = DD; }
    else if (r < RQKV + RWO)         { r -= RQKV; s = Wo + (size_t)r * DD; d = wo2 + (size_t)r * 2 * DD; K = DD; }
    else if (r < RQKV + RWO + RW1)   { r -= RQKV + RWO; s = W1 + (size_t)r * DD; d = w12 + (size_t)r * 2 * DD; K = DD; }
    else                             { r -= RQKV + RWO + RW1; s = W2 + (size_t)r * FFN; d = w22 + (size_t)r * 2 * FFN; K = FFN; }
    for (int c = threadIdx.x; c < K; c += 256)
        split2(s[c], &d[c], &d[K + c]);
}

// fp32 -> fp16 plain convert
__global__ __launch_bounds__(256) void cvt_half_kernel(
    const float* __restrict__ s, __half* __restrict__ d, int n)
{
    int i = (blockIdx.x * 256 + threadIdx.x) * 4;
    if (i < n) {
        float4 v = *(const float4*)(s + i);
        d[i + 0] = __float2half_rn(v.x);
        d[i + 1] = __float2half_rn(v.y);
        d[i + 2] = __float2half_rn(v.z);
        d[i + 3] = __float2half_rn(v.w);
    }
}

// ---------------------------------------------------------------------------
// Tensor-core GEMM: C[M,N] = A * B^T + bias.
// PASSES=3 (bf16x3): A2,B2 = [rows, 2K] bf16 hi|lo; hi*hi + hi*lo + lo*hi.
// PASSES=1 (fp16):   A2,B2 = [rows, K] fp16, single pass.
// NTH threads (NTH/32 warps: (NTH/128) x 4 grid), warp tile WMxWN,
// K-chunk 32, 3-buffer cp.async pipeline, lookahead 2.
// smem rows: 32 elems = 64B + 16B pad = 80B (conflict-free ldmatrix).
// 256-thread variants target 2 CTAs/SM (regs capped at 128).
// ---------------------------------------------------------------------------
template<int TM, int TN, int PASSES, int NTH>
__global__ __launch_bounds__(NTH, (NTH == 256) ? 2 : 1)
void gemm_mma(const __nv_bfloat16* __restrict__ A2,
              const __nv_bfloat16* __restrict__ B2,
              const float* __restrict__ bias,
              float* __restrict__ C, int N, int K)
{
    constexpr bool F16 = (PASSES == 1);
    constexpr int WARPS_M = NTH / 128;        // 2 or 4
    constexpr int WM = TM / WARPS_M, WN = TN / 4;
    constexpr int MI = WM / 16;
    constexpr int NI = WN / 8;
    constexpr int NB = WN / 16;
    constexpr int AT = (PASSES == 3) ? 2 : 1;
    constexpr int SA = AT * TM * 80;
    constexpr int SB = AT * TN * 80;
    constexpr int STAGE = SA + SB;
    constexpr int ACH = AT * TM * 4;
    constexpr int NCH = ACH + AT * TN * 4;

    extern __shared__ __align__(128) char dsm[];
    uint32_t sbase = smem_to_u32(dsm);

    int tid = threadIdx.x, lane = tid & 31, warp = tid >> 5;
    int wm = warp >> 2, wn = warp & 3;
    size_t bm = (size_t)blockIdx.y * TM;
    size_t bn = (size_t)blockIdx.x * TN;
    int astr = (PASSES == 3) ? 2 * K : K;
    int nk = K / 32;

    float acc[MI][NI][4];
    #pragma unroll
    for (int mi = 0; mi < MI; mi++)
        #pragma unroll
        for (int ni = 0; ni < NI; ni++)
            #pragma unroll
            for (int j = 0; j < 4; j++) acc[mi][ni][j] = 0.f;

    auto load_stage = [&](int it) {
        int buf = it % 3;
        int kc = it * 32;
        uint32_t sAp = sbase + buf * STAGE;
        uint32_t sBp = sAp + SA;
        #pragma unroll
        for (int ii = 0; ii < NCH / NTH; ii++) {
            int i = tid + ii * NTH;
            if (i < ACH) {
                int row, half, seg;
                if (PASSES == 3) { row = i >> 3; half = (i >> 2) & 1; seg = i & 3; }
                else             { row = i >> 2; half = 0;            seg = i & 3; }
                cp16(sAp + (uint32_t)(half * (TM * 80) + row * 80 + seg * 16),
                     A2 + (bm + row) * (size_t)astr + half * K + kc + seg * 8);
            } else {
                int j = i - ACH;
                int row, half, seg;
                if (PASSES == 3) { row = j >> 3; half = (j >> 2) & 1; seg = j & 3; }
                else             { row = j >> 2; half = 0;            seg = j & 3; }
                cp16(sBp + (uint32_t)(half * (TN * 80) + row * 80 + seg * 16),
                     B2 + (bn + row) * (size_t)astr + half * K + kc + seg * 8);
            }
        }
    };

    load_stage(0); CP_COMMIT();
    if (nk > 1) load_stage(1);
    CP_COMMIT();

    for (int it = 0; it < nk; it++) {
        CP_WAIT1();
        __syncthreads();
        if (it + 2 < nk) load_stage(it + 2);
        CP_COMMIT();

        int buf = it % 3;
        uint32_t sAhi = sbase + buf * STAGE;
        uint32_t sAlo = sAhi + TM * 80;
        uint32_t sBhi = sAhi + SA;
        uint32_t sBlo = sBhi + TN * 80;

        #pragma unroll
        for (int ks = 0; ks < 2; ks++) {
            int arow = wm * WM + (lane & 15);
            int achk = ks * 2 + (lane >> 4);
            uint32_t aoff = (uint32_t)(arow * 80 + achk * 16);
            int sel = lane >> 3, within = lane & 7;
            int nrow = wn * WN + within + ((sel >> 1) << 3);
            int bchk = ks * 2 + (sel & 1);
            uint32_t boff = (uint32_t)(nrow * 80 + bchk * 16);

            uint32_t ahf[MI][4], bhf[NB][4];
            #pragma unroll
            for (int mi = 0; mi < MI; mi++)
                ldm_x4(ahf[mi], sAhi + aoff + mi * 16 * 80);
            #pragma unroll
            for (int n2 = 0; n2 < NB; n2++)
                ldm_x4(bhf[n2], sBhi + boff + n2 * 16 * 80);

            // pass 0: hi * hi
            #pragma unroll
            for (int mi = 0; mi < MI; mi++)
                #pragma unroll
                for (int ni = 0; ni < NI; ni++)
                    mma16816<F16>(acc[mi][ni], ahf[mi],
                                  bhf[ni >> 1][(ni & 1) * 2],
                                  bhf[ni >> 1][(ni & 1) * 2 + 1]);
            if (PASSES == 3) {
                uint32_t blf[NB][4];
                #pragma unroll
                for (int n2 = 0; n2 < NB; n2++)
                    ldm_x4(blf[n2], sBlo + boff + n2 * 16 * 80);
                // pass 1: Ahi * Blo
                #pragma unroll
                for (int mi = 0; mi < MI; mi++)
                    #pragma unroll
                    for (int ni = 0; ni < NI; ni++)
                        mma16816<F16>(acc[mi][ni], ahf[mi],
                                      blf[ni >> 1][(ni & 1) * 2],
                                      blf[ni >> 1][(ni & 1) * 2 + 1]);
                uint32_t alf[MI][4];
                #pragma unroll
                for (int mi = 0; mi < MI; mi++)
                    ldm_x4(alf[mi], sAlo + aoff + mi * 16 * 80);
                // pass 2: Alo * Bhi
                #pragma unroll
                for (int mi = 0; mi < MI; mi++)
                    #pragma unroll
                    for (int ni = 0; ni < NI; ni++)
                        mma16816<F16>(acc[mi][ni], alf[mi],
                                      bhf[ni >> 1][(ni & 1) * 2],
                                      bhf[ni >> 1][(ni & 1) * 2 + 1]);
            }
        }
    }

    // epilogue
    int r0 = (int)bm + wm * WM + (lane >> 2);
    int c0 = (int)bn + wn * WN + (lane & 3) * 2;
    #pragma unroll
    for (int mi = 0; mi < MI; mi++) {
        #pragma unroll
        for (int ni = 0; ni < NI; ni++) {
            int row = r0 + mi * 16;
            int col = c0 + ni * 8;
            float bx = 0.f, by = 0.f;
            if (bias) { bx = bias[col]; by = bias[col + 1]; }
            float2 lo, hi;
            lo.x = acc[mi][ni][0] + bx; lo.y = acc[mi][ni][1] + by;
            hi.x = acc[mi][ni][2] + bx; hi.y = acc[mi][ni][3] + by;
            *(float2*)(C + (size_t)row * N + col) = lo;
            *(float2*)(C + (size_t)(row + 8) * N + col) = hi;
        }
    }
}

// ---------------------------------------------------------------------------
// Embedding + positional encoding -> X fp32 and X2 bf16 split
// ---------------------------------------------------------------------------
__global__ __launch_bounds__(128) void embed_kernel(
    const int* __restrict__ ids, const float* __restrict__ emb,
    float* __restrict__ x, __nv_bfloat16* __restrict__ x2)
{
    int n = blockIdx.x;
    int s = n & (SS - 1);
    int id = ids[n];
    const float Cc = -0.01798894591761708f;  // -ln(10000)/512
    #pragma unroll
    for (int k = 0; k < 4; k++) {
        int d = threadIdx.x + k * 128;
        float ang = (float)s * expf((float)(d & ~1) * Cc);
        float pe = (d & 1) ? cosf(ang) : sinf(ang);
        float v = emb[(size_t)id * DD + d] + pe;
        x[(size_t)n * DD + d] = v;
        split2(v, &x2[(size_t)n * 2 * DD + d], &x2[(size_t)n * 2 * DD + DD + d]);
    }
}

// ---------------------------------------------------------------------------
// Windowed attention, exact fp32.
// Block = (32 queries, head, batch), 256 threads. 8-lane group per query.
// Score phase: lanes split KEYS; each lane does a full 64-dim float4 dot
// (K rows from gmem, L1-hot; Q broadcast from smem). No per-key shuffles.
// Scores in smem (pitch 516 to dodge group bank aliasing); exp/sum; then
// V pass with lanes split over dims. Output bf16 hi/lo split.
// ---------------------------------------------------------------------------
#define SCP 516                                   // score row pitch (floats)
#define ATTN_SMEM (32*SCP*4 + 32*64*4)            // 74.2 KB
__global__ __launch_bounds__(256) void attn_kernel(
    const float* __restrict__ qkv, __nv_bfloat16* __restrict__ out2)
{
    extern __shared__ float asmem[];
    float* sc = asmem;                 // [32][SCP]
    float* qs = asmem + 32 * SCP;      // [32][64]

    int s0 = blockIdx.x * 32, h = blockIdx.y, b = blockIdx.z;
    int win = (h + 1) * 64;
    int tid = threadIdx.x, lane = tid & 31, warp = tid >> 5;
    int qg = lane >> 3, sl = lane & 7;
    int q = warp * 4 + qg;             // 0..31
    int sq = s0 + q;
    int j0 = sq - win + 1; if (j0 < 0) j0 = 0;
    int cnt = sq + 1 - j0;

    const float* base = qkv + (size_t)b * SS * (3 * DD);

    // stage Q tile
    for (int i = tid; i < 32 * 64; i += 256) {
        int qq = i >> 6, d = i & 63;
        qs[i] = base[(size_t)(s0 + qq) * (3 * DD) + h * 64 + d];
    }
    __syncthreads();

    // ---- scores: lane sl handles keys i = kb + sl ----
    const float4* q4 = (const float4*)(qs + q * 64);
    float m = -3.4e38f;
    for (int kb = 0; kb < cnt; kb += 8) {
        int i = kb + sl;
        int key = j0 + i; if (key > sq) key = sq;   // clamp OOB lanes
        const float4* kr = (const float4*)(base + (size_t)key * (3 * DD) + DD + h * 64);
        float s = 0.f;
        #pragma unroll
        for (int d4 = 0; d4 < 16; d4++) {
            float4 kk = kr[d4];
            float4 qv = q4[d4];
            s = fmaf(kk.x, qv.x, fmaf(kk.y, qv.y, fmaf(kk.z, qv.z, fmaf(kk.w, qv.w, s))));
        }
        if (i < cnt) {
            s *= 0.125f;                             // 1/sqrt(64)
            sc[q * SCP + i] = s;
            m = fmaxf(m, s);
        }
    }
    m = fmaxf(m, __shfl_xor_sync(0xffffffffu, m, 1));
    m = fmaxf(m, __shfl_xor_sync(0xffffffffu, m, 2));
    m = fmaxf(m, __shfl_xor_sync(0xffffffffu, m, 4));

    // ---- exp + sum ----
    float ssum = 0.f;
    for (int i = sl; i < cnt; i += 8) {
        float e = expf(sc[q * SCP + i] - m);
        sc[q * SCP + i] = e;
        ssum += e;
    }
    ssum += __shfl_xor_sync(0xffffffffu, ssum, 1);
    ssum += __shfl_xor_sync(0xffffffffu, ssum, 2);
    ssum += __shfl_xor_sync(0xffffffffu, ssum, 4);
    float inv = 1.0f / ssum;
    __syncwarp();

    // ---- V pass: lane owns dims [sl*8, sl*8+8) ----
    float4 a0 = {0,0,0,0}, a1 = {0,0,0,0};
    const float* vb = base + (size_t)j0 * (3 * DD) + 2 * DD + h * 64 + sl * 8;
    for (int i = 0; i < cnt; i++) {
        float p = sc[q * SCP + i];
        const float4* vr = (const float4*)(vb + (size_t)i * (3 * DD));
        float4 v0 = vr[0], v1 = vr[1];
        a0.x = fmaf(p, v0.x, a0.x); a0.y = fmaf(p, v0.y, a0.y);
        a0.z = fmaf(p, v0.z, a0.z); a0.w = fmaf(p, v0.w, a0.w);
        a1.x = fmaf(p, v1.x, a1.x); a1.y = fmaf(p, v1.y, a1.y);
        a1.z = fmaf(p, v1.z, a1.z); a1.w = fmaf(p, v1.w, a1.w);
    }
    size_t n = (size_t)(b * SS + sq);
    __nv_bfloat16* oh = out2 + n * 2 * DD + h * 64 + sl * 8;
    __nv_bfloat16* ol = oh + DD;
    float vals[8] = {a0.x, a0.y, a0.z, a0.w, a1.x, a1.y, a1.z, a1.w};
    #pragma unroll
    for (int k = 0; k < 8; k++)
        split2(vals[k] * inv, &oh[k], &ol[k]);
}

// ---------------------------------------------------------------------------
// (residual) + LayerNorm; optional fp32 / bf16-split / fp16 outputs
// ---------------------------------------------------------------------------
__global__ __launch_bounds__(128) void ln_kernel(
    const float* __restrict__ xin, const float* __restrict__ res,
    const float* __restrict__ g, const float* __restrict__ b,
    float* __restrict__ out, __nv_bfloat16* __restrict__ out2,
    __half* __restrict__ outh)
{
    int row = blockIdx.x;
    const float* xr = xin + (size_t)row * DD;
    const float* rr = res ? res + (size_t)row * DD : nullptr;
    int tid = threadIdx.x;
    float v[4];
    float s = 0.f, s2 = 0.f;
    #pragma unroll
    for (int k = 0; k < 4; k++) {
        int d = tid + k * 128;
        float t = xr[d];
        if (rr) t += rr[d];
        v[k] = t; s += t; s2 += t * t;
    }
    __shared__ float sh[2][4];
    #pragma unroll
    for (int o = 16; o; o >>= 1) {
        s  += __shfl_xor_sync(0xffffffffu, s, o);
        s2 += __shfl_xor_sync(0xffffffffu, s2, o);
    }
    if ((tid & 31) == 0) { sh[0][tid >> 5] = s; sh[1][tid >> 5] = s2; }
    __syncthreads();
    s  = sh[0][0] + sh[0][1] + sh[0][2] + sh[0][3];
    s2 = sh[1][0] + sh[1][1] + sh[1][2] + sh[1][3];
    float mean = s * (1.0f / 512.0f);
    float var = s2 * (1.0f / 512.0f) - mean * mean;
    float rstd = rsqrtf(var + 1e-5f);
    #pragma unroll
    for (int k = 0; k < 4; k++) {
        int d = tid + k * 128;
        float o = (v[k] - mean) * rstd * g[d] + b[d];
        if (out) out[(size_t)row * DD + d] = o;
        if (out2) split2(o, &out2[(size_t)row * 2 * DD + d],
                            &out2[(size_t)row * 2 * DD + DD + d]);
        if (outh) outh[(size_t)row * DD + d] = __float2half_rn(o);
    }
}

// ---------------------------------------------------------------------------
// SwiGLU -> bf16 split directly
// ---------------------------------------------------------------------------
__global__ __launch_bounds__(256) void swiglu_kernel(
    const float* __restrict__ h, __nv_bfloat16* __restrict__ ff2)
{
    int n = blockIdx.x;
    const float* hr = h + (size_t)n * (2 * FFN);
    __nv_bfloat16* fr = ff2 + (size_t)n * (2 * FFN);
    for (int f = threadIdx.x; f < FFN; f += 256) {
        float u = hr[f], gg = hr[FFN + f];
        float v = u * gg / (1.0f + expf(-gg));
        split2(v, &fr[f], &fr[FFN + f]);
    }
}

// ---------------------------------------------------------------------------
// Launch
// ---------------------------------------------------------------------------
#define SMEM_QKV (3 * (2*64*80 + 2*128*80))   // 92160, <64,128,3,256>
#define SMEM_WO  (3 * (2*64*80 + 2*64*80))    // 61440, <64,64,3,256>
#define SMEM_LM  (3 * (256*80 + 128*80))      // 92160, <256,128,1,512>

extern "C" void kernel_launch(void* const* d_in, const int* in_sizes, int n_in,
                              void* d_out, int out_size)
{
    const int*   ids   = (const int*)  d_in[0];
    const float* emb   = (const float*)d_in[1];
    const float* Wqkv  = (const float*)d_in[2];
    const float* bqkv  = (const float*)d_in[3];
    const float* Wo    = (const float*)d_in[4];
    const float* bo    = (const float*)d_in[5];
    const float* W1    = (const float*)d_in[6];
    const float* b1    = (const float*)d_in[7];
    const float* W2    = (const float*)d_in[8];
    const float* b2    = (const float*)d_in[9];
    const float* ln1_g = (const float*)d_in[10];
    const float* ln1_b = (const float*)d_in[11];
    const float* ln2_g = (const float*)d_in[12];
    const float* ln2_b = (const float*)d_in[13];
    const float* lnf_g = (const float*)d_in[14];
    const float* lnf_b = (const float*)d_in[15];
    float* out = (float*)d_out;

    float *X, *QKV, *TMP, *HB;
    __nv_bfloat16 *wqkv2, *wo2, *w12, *w22, *x2, *att2, *ff2;
    __half *embh, *lnfh;
    cudaGetSymbolAddress((void**)&X,    g_X);
    cudaGetSymbolAddress((void**)&QKV,  g_QKV);
    cudaGetSymbolAddress((void**)&TMP,  g_TMP);
    cudaGetSymbolAddress((void**)&HB,   g_HB);
    cudaGetSymbolAddress((void**)&wqkv2,g_wqkv2);
    cudaGetSymbolAddress((void**)&wo2,  g_wo2);
    cudaGetSymbolAddress((void**)&w12,  g_w12);
    cudaGetSymbolAddress((void**)&w22,  g_w22);
    cudaGetSymbolAddress((void**)&x2,   g_x2);
    cudaGetSymbolAddress((void**)&att2, g_att2);
    cudaGetSymbolAddress((void**)&ff2,  g_ff2);
    cudaGetSymbolAddress((void**)&embh, g_embh);
    cudaGetSymbolAddress((void**)&lnfh, g_lnfh);

    cudaFuncSetAttribute((const void*)gemm_mma<64,128,3,256>,
                         cudaFuncAttributeMaxDynamicSharedMemorySize, SMEM_QKV);
    cudaFuncSetAttribute((const void*)gemm_mma<64,64,3,256>,
                         cudaFuncAttributeMaxDynamicSharedMemorySize, SMEM_WO);
    cudaFuncSetAttribute((const void*)gemm_mma<256,128,1,512>,
                         cudaFuncAttributeMaxDynamicSharedMemorySize, SMEM_LM);
    cudaFuncSetAttribute((const void*)attn_kernel,
                         cudaFuncAttributeMaxDynamicSharedMemorySize, ATTN_SMEM);

    // weight preprocessing (graph-replayed each call)
    prep_split<<<RQKV + RWO + RW1 + RW2, 256>>>(Wqkv, Wo, W1, W2,
                                                wqkv2, wo2, w12, w22);
    cvt_half_kernel<<<(VV * DD) / 1024, 256>>>(emb, embh, VV * DD);

    embed_kernel<<<NT, 128>>>(ids, emb, X, x2);

    for (int l = 0; l < LL; l++) {
        // QKV: [2048,512] x [1536,512]^T   (64x128, 384 blocks, 2 CTA/SM)
        gemm_mma<64,128,3,256><<<dim3(12, 32), 256, SMEM_QKV>>>(
            x2, wqkv2 + (size_t)l * 3 * DD * 2 * DD,
            bqkv + (size_t)l * 3 * DD, QKV, 3 * DD, DD);
        // windowed attention -> att2 (bf16 split)
        attn_kernel<<<dim3(SS / 32, HH, BB), 256, ATTN_SMEM>>>(QKV, att2);
        // Wo: [2048,512] x [512,512]^T   (64x64, 256 blocks)
        gemm_mma<64,64,3,256><<<dim3(8, 32), 256, SMEM_WO>>>(
            att2, wo2 + (size_t)l * DD * 2 * DD,
            bo + (size_t)l * DD, TMP, DD, DD);
        // x = LN(x + attn_out)
        ln_kernel<<<NT, 128>>>(X, TMP, ln1_g + (size_t)l * DD,
                               ln1_b + (size_t)l * DD, X, x2, nullptr);
        // W1: [2048,512] x [4096,512]^T   (64x128, 1024 blocks)
        gemm_mma<64,128,3,256><<<dim3(32, 32), 256, SMEM_QKV>>>(
            x2, w12 + (size_t)l * 2 * FFN * 2 * DD,
            b1 + (size_t)l * 2 * FFN, HB, 2 * FFN, DD);
        swiglu_kernel<<<NT, 256>>>(HB, ff2);
        // W2: [2048,2048] x [512,2048]^T  (64x64, 256 blocks)
        gemm_mma<64,64,3,256><<<dim3(8, 32), 256, SMEM_WO>>>(
            ff2, w22 + (size_t)l * DD * 2 * FFN,
            b2 + (size_t)l * DD, TMP, DD, FFN);
        // x = LN(x + ff_out)
        ln_kernel<<<NT, 128>>>(X, TMP, ln2_g + (size_t)l * DD,
                               ln2_b + (size_t)l * DD, X, x2, nullptr);
    }

    // final LN -> fp16, tied LM head (fp16 single-pass, 256x128, 2000 blocks)
    ln_kernel<<<NT, 128>>>(X, nullptr, lnf_g, lnf_b, nullptr, nullptr, lnfh);
    gemm_mma<256,128,1,512><<<dim3(VV / 128, NT / 256), 512, SMEM_LM>>>(
        (const __nv_bfloat16*)lnfh, (const __nv_bfloat16*)embh,
        nullptr, out, VV, DD);
}

// round 7
// speedup vs baseline: 1.5231x; 1.5231x over previous
#include <cuda_runtime.h>
#include <cuda_bf16.h>
#include <cuda_fp16.h>
#include <stdint.h>
#include <math.h>

// Problem constants
#define BB 2
#define SS 1024
#define DD 512
#define HH 8
#define LL 6
#define VV 32000
#define FFN 2048
#define NT (BB*SS)          // 2048 tokens

// ---------------------------------------------------------------------------
// Device scratch (static, no allocations)
// ---------------------------------------------------------------------------
__device__ float g_X  [NT*DD];
__device__ float g_QKV[NT*3*DD];
__device__ float g_TMP[NT*DD];
__device__ float g_HB [NT*2*FFN];

__device__ __nv_bfloat16 g_wqkv2[(size_t)LL*3*DD*2*DD];   // [rows, 2K] hi|lo
__device__ __nv_bfloat16 g_wo2  [(size_t)LL*DD*2*DD];
__device__ __nv_bfloat16 g_w12  [(size_t)LL*2*FFN*2*DD];
__device__ __nv_bfloat16 g_w22  [(size_t)LL*DD*2*FFN];
__device__ __nv_bfloat16 g_x2   [(size_t)NT*2*DD];
__device__ __nv_bfloat16 g_att2 [(size_t)NT*2*DD];
__device__ __nv_bfloat16 g_ff2  [(size_t)NT*2*FFN];
__device__ __half        g_embh [(size_t)VV*DD];          // fp16 for LM head
__device__ __half        g_lnfh [(size_t)NT*DD];

// ---------------------------------------------------------------------------
// PTX helpers (baseline ISA only: cp.async, ldmatrix, mma.sync)
// ---------------------------------------------------------------------------
__device__ __forceinline__ uint32_t smem_to_u32(const void* p) {
    uint32_t a;
    asm("{ .reg .u64 t; cvta.to.shared.u64 t, %1; cvt.u32.u64 %0, t; }"
        : "=r"(a) : "l"(p));
    return a;
}
__device__ __forceinline__ void cp16(uint32_t dst, const void* src) {
    asm volatile("cp.async.cg.shared.global [%0], [%1], 16;\n" :: "r"(dst), "l"(src) : "memory");
}
#define CP_COMMIT()  asm volatile("cp.async.commit_group;" ::: "memory")
#define CP_WAIT1()   asm volatile("cp.async.wait_group 1;" ::: "memory")

__device__ __forceinline__ void ldm_x4(uint32_t* r, uint32_t addr) {
    asm volatile("ldmatrix.sync.aligned.m8n8.x4.shared.b16 {%0,%1,%2,%3}, [%4];"
        : "=r"(r[0]), "=r"(r[1]), "=r"(r[2]), "=r"(r[3]) : "r"(addr));
}
template<bool F16>
__device__ __forceinline__ void mma16816(float* c, const uint32_t* a,
                                         uint32_t b0, uint32_t b1) {
    if (F16)
        asm volatile(
            "mma.sync.aligned.m16n8k16.row.col.f32.f16.f16.f32 "
            "{%0,%1,%2,%3}, {%4,%5,%6,%7}, {%8,%9}, {%0,%1,%2,%3};"
            : "+f"(c[0]), "+f"(c[1]), "+f"(c[2]), "+f"(c[3])
            : "r"(a[0]), "r"(a[1]), "r"(a[2]), "r"(a[3]), "r"(b0), "r"(b1));
    else
        asm volatile(
            "mma.sync.aligned.m16n8k16.row.col.f32.bf16.bf16.f32 "
            "{%0,%1,%2,%3}, {%4,%5,%6,%7}, {%8,%9}, {%0,%1,%2,%3};"
            : "+f"(c[0]), "+f"(c[1]), "+f"(c[2]), "+f"(c[3])
            : "r"(a[0]), "r"(a[1]), "r"(a[2]), "r"(a[3]), "r"(b0), "r"(b1));
}

// ---------------------------------------------------------------------------
// bf16 hi/lo split helpers
// ---------------------------------------------------------------------------
__device__ __forceinline__ void split2(float x, __nv_bfloat16* hi_p, __nv_bfloat16* lo_p) {
    __nv_bfloat16 h = __float2bfloat16_rn(x);
    *hi_p = h;
    *lo_p = __float2bfloat16_rn(x - __bfloat162float(h));
}

// Fused weight split: all 4 weight tensors in one launch.
#define RQKV (LL*3*DD)
#define RWO  (LL*DD)
#define RW1  (LL*2*FFN)
#define RW2  (LL*DD)
__global__ __launch_bounds__(256) void prep_split(
    const float* __restrict__ Wqkv, const float* __restrict__ Wo,
    const float* __restrict__ W1,   const float* __restrict__ W2,
    __nv_bfloat16* __restrict__ wqkv2, __nv_bfloat16* __restrict__ wo2,
    __nv_bfloat16* __restrict__ w12,   __nv_bfloat16* __restrict__ w22)
{
    int r = blockIdx.x;
    const float* s; __nv_bfloat16* d; int K;
    if (r < RQKV)                    { s = Wqkv + (size_t)r * DD; d = wqkv2 + (size_t)r * 2 * DD; K = DD; }
    else if (r < RQKV + RWO)         { r -= RQKV; s = Wo + (size_t)r * DD; d = wo2 + (size_t)r * 2 * DD; K = DD; }
    else if (r < RQKV + RWO + RW1)   { r -= RQKV + RWO; s = W1 + (size_t)r * DD; d = w12 + (size_t)r * 2 * DD; K = DD; }
    else                             { r -= RQKV + RWO + RW1; s = W2 + (size_t)r * FFN; d = w22 + (size_t)r * 2 * FFN; K = FFN; }
    for (int c = threadIdx.x; c < K; c += 256)
        split2(s[c], &d[c], &d[K + c]);
}

// fp32 -> fp16 plain convert
__global__ __launch_bounds__(256) void cvt_half_kernel(
    const float* __restrict__ s, __half* __restrict__ d, int n)
{
    int i = (blockIdx.x * 256 + threadIdx.x) * 4;
    if (i < n) {
        float4 v = *(const float4*)(s + i);
        d[i + 0] = __float2half_rn(v.x);
        d[i + 1] = __float2half_rn(v.y);
        d[i + 2] = __float2half_rn(v.z);
        d[i + 3] = __float2half_rn(v.w);
    }
}

// ---------------------------------------------------------------------------
// Tensor-core GEMM: C[M,N] = A * B^T + bias.
// PASSES=3 (bf16x3): A2,B2 = [rows, 2K] bf16 hi|lo; hi*hi + hi*lo + lo*hi.
// PASSES=1 (fp16):   A2,B2 = [rows, K] fp16, single pass.
// 256 threads (8 warps, 2m x 4n), warp tile (TM/2) x (TN/4), K-chunk 32,
// 3-buffer cp.async pipeline, lookahead 2.
// smem rows: 32 elems = 64B + 16B pad = 80B (conflict-free ldmatrix).
// MINB=2 caps regs at 128 for 2 CTAs/SM (use only when acc regs are small).
// ---------------------------------------------------------------------------
template<int TM, int TN, int PASSES, int MINB>
__global__ __launch_bounds__(256, MINB)
void gemm_mma(const __nv_bfloat16* __restrict__ A2,
              const __nv_bfloat16* __restrict__ B2,
              const float* __restrict__ bias,
              float* __restrict__ C, int N, int K)
{
    constexpr bool F16 = (PASSES == 1);
    constexpr int WM = TM / 2, WN = TN / 4;
    constexpr int MI = WM / 16;
    constexpr int NI = WN / 8;
    constexpr int NB = WN / 16;
    constexpr int AT = (PASSES == 3) ? 2 : 1;
    constexpr int SA = AT * TM * 80;
    constexpr int SB = AT * TN * 80;
    constexpr int STAGE = SA + SB;
    constexpr int ACH = AT * TM * 4;
    constexpr int NCH = ACH + AT * TN * 4;

    extern __shared__ __align__(128) char dsm[];
    uint32_t sbase = smem_to_u32(dsm);

    int tid = threadIdx.x, lane = tid & 31, warp = tid >> 5;
    int wm = warp >> 2, wn = warp & 3;
    size_t bm = (size_t)blockIdx.y * TM;
    size_t bn = (size_t)blockIdx.x * TN;
    int astr = (PASSES == 3) ? 2 * K : K;
    int nk = K / 32;

    float acc[MI][NI][4];
    #pragma unroll
    for (int mi = 0; mi < MI; mi++)
        #pragma unroll
        for (int ni = 0; ni < NI; ni++)
            #pragma unroll
            for (int j = 0; j < 4; j++) acc[mi][ni][j] = 0.f;

    auto load_stage = [&](int it) {
        int buf = it % 3;
        int kc = it * 32;
        uint32_t sAp = sbase + buf * STAGE;
        uint32_t sBp = sAp + SA;
        #pragma unroll
        for (int ii = 0; ii < NCH / 256; ii++) {
            int i = tid + ii * 256;
            if (i < ACH) {
                int row, half, seg;
                if (PASSES == 3) { row = i >> 3; half = (i >> 2) & 1; seg = i & 3; }
                else             { row = i >> 2; half = 0;            seg = i & 3; }
                cp16(sAp + (uint32_t)(half * (TM * 80) + row * 80 + seg * 16),
                     A2 + (bm + row) * (size_t)astr + half * K + kc + seg * 8);
            } else {
                int j = i - ACH;
                int row, half, seg;
                if (PASSES == 3) { row = j >> 3; half = (j >> 2) & 1; seg = j & 3; }
                else             { row = j >> 2; half = 0;            seg = j & 3; }
                cp16(sBp + (uint32_t)(half * (TN * 80) + row * 80 + seg * 16),
                     B2 + (bn + row) * (size_t)astr + half * K + kc + seg * 8);
            }
        }
    };

    load_stage(0); CP_COMMIT();
    if (nk > 1) load_stage(1);
    CP_COMMIT();

    for (int it = 0; it < nk; it++) {
        CP_WAIT1();
        __syncthreads();
        if (it + 2 < nk) load_stage(it + 2);
        CP_COMMIT();

        int buf = it % 3;
        uint32_t sAhi = sbase + buf * STAGE;
        uint32_t sAlo = sAhi + TM * 80;
        uint32_t sBhi = sAhi + SA;
        uint32_t sBlo = sBhi + TN * 80;

        #pragma unroll
        for (int ks = 0; ks < 2; ks++) {
            int arow = wm * WM + (lane & 15);
            int achk = ks * 2 + (lane >> 4);
            uint32_t aoff = (uint32_t)(arow * 80 + achk * 16);
            int sel = lane >> 3, within = lane & 7;
            int nrow = wn * WN + within + ((sel >> 1) << 3);
            int bchk = ks * 2 + (sel & 1);
            uint32_t boff = (uint32_t)(nrow * 80 + bchk * 16);

            uint32_t ahf[MI][4], bhf[NB][4];
            #pragma unroll
            for (int mi = 0; mi < MI; mi++)
                ldm_x4(ahf[mi], sAhi + aoff + mi * 16 * 80);
            #pragma unroll
            for (int n2 = 0; n2 < NB; n2++)
                ldm_x4(bhf[n2], sBhi + boff + n2 * 16 * 80);

            // pass 0: hi * hi
            #pragma unroll
            for (int mi = 0; mi < MI; mi++)
                #pragma unroll
                for (int ni = 0; ni < NI; ni++)
                    mma16816<F16>(acc[mi][ni], ahf[mi],
                                  bhf[ni >> 1][(ni & 1) * 2],
                                  bhf[ni >> 1][(ni & 1) * 2 + 1]);
            if (PASSES == 3) {
                uint32_t blf[NB][4];
                #pragma unroll
                for (int n2 = 0; n2 < NB; n2++)
                    ldm_x4(blf[n2], sBlo + boff + n2 * 16 * 80);
                // pass 1: Ahi * Blo
                #pragma unroll
                for (int mi = 0; mi < MI; mi++)
                    #pragma unroll
                    for (int ni = 0; ni < NI; ni++)
                        mma16816<F16>(acc[mi][ni], ahf[mi],
                                      blf[ni >> 1][(ni & 1) * 2],
                                      blf[ni >> 1][(ni & 1) * 2 + 1]);
                uint32_t alf[MI][4];
                #pragma unroll
                for (int mi = 0; mi < MI; mi++)
                    ldm_x4(alf[mi], sAlo + aoff + mi * 16 * 80);
                // pass 2: Alo * Bhi
                #pragma unroll
                for (int mi = 0; mi < MI; mi++)
                    #pragma unroll
                    for (int ni = 0; ni < NI; ni++)
                        mma16816<F16>(acc[mi][ni], alf[mi],
                                      bhf[ni >> 1][(ni & 1) * 2],
                                      bhf[ni >> 1][(ni & 1) * 2 + 1]);
            }
        }
    }

    // epilogue
    int r0 = (int)bm + wm * WM + (lane >> 2);
    int c0 = (int)bn + wn * WN + (lane & 3) * 2;
    #pragma unroll
    for (int mi = 0; mi < MI; mi++) {
        #pragma unroll
        for (int ni = 0; ni < NI; ni++) {
            int row = r0 + mi * 16;
            int col = c0 + ni * 8;
            float bx = 0.f, by = 0.f;
            if (bias) { bx = bias[col]; by = bias[col + 1]; }
            float2 lo, hi;
            lo.x = acc[mi][ni][0] + bx; lo.y = acc[mi][ni][1] + by;
            hi.x = acc[mi][ni][2] + bx; hi.y = acc[mi][ni][3] + by;
            *(float2*)(C + (size_t)row * N + col) = lo;
            *(float2*)(C + (size_t)(row + 8) * N + col) = hi;
        }
    }
}

// ---------------------------------------------------------------------------
// Embedding + positional encoding -> X fp32 and X2 bf16 split
// ---------------------------------------------------------------------------
__global__ __launch_bounds__(128) void embed_kernel(
    const int* __restrict__ ids, const float* __restrict__ emb,
    float* __restrict__ x, __nv_bfloat16* __restrict__ x2)
{
    int n = blockIdx.x;
    int s = n & (SS - 1);
    int id = ids[n];
    const float Cc = -0.01798894591761708f;  // -ln(10000)/512
    #pragma unroll
    for (int k = 0; k < 4; k++) {
        int d = threadIdx.x + k * 128;
        float ang = (float)s * expf((float)(d & ~1) * Cc);
        float pe = (d & 1) ? cosf(ang) : sinf(ang);
        float v = emb[(size_t)id * DD + d] + pe;
        x[(size_t)n * DD + d] = v;
        split2(v, &x2[(size_t)n * 2 * DD + d], &x2[(size_t)n * 2 * DD + DD + d]);
    }
}

// ---------------------------------------------------------------------------
// Windowed attention (R5 version): 4 queries/block, warp-per-query.
// Output: bf16 split.
// ---------------------------------------------------------------------------
__global__ __launch_bounds__(128) void attn_kernel(
    const float* __restrict__ qkv, __nv_bfloat16* __restrict__ out2)
{
    int s0 = blockIdx.x * 4, h = blockIdx.y, b = blockIdx.z;
    int win = (h + 1) * 64;
    int tid = threadIdx.x, lane = tid & 31, warp = tid >> 5;

    __shared__ float sc[4][512];
    __shared__ float inv_s[4];

    const float* base = qkv + (size_t)b * SS * (3 * DD);

    int sq = s0 + warp;
    int j0 = sq - win + 1; if (j0 < 0) j0 = 0;
    int cnt = sq + 1 - j0;

    float2 qq = *(const float2*)(base + (size_t)sq * (3 * DD) + h * 64 + lane * 2);

    float m = -3.4e38f;
    for (int i = 0; i < cnt; i++) {
        const float* kp = base + (size_t)(j0 + i) * (3 * DD) + DD + h * 64;
        float2 kk = *(const float2*)(kp + lane * 2);
        float d = kk.x * qq.x + kk.y * qq.y;
        #pragma unroll
        for (int o = 16; o; o >>= 1) d += __shfl_xor_sync(0xffffffffu, d, o);
        d *= 0.125f;                              // 1/sqrt(64)
        if (lane == 0) sc[warp][i] = d;
        m = fmaxf(m, d);
    }
    __syncwarp();
    float ssum = 0.f;
    for (int i = lane; i < cnt; i += 32) {
        float e = expf(sc[warp][i] - m);
        sc[warp][i] = e;
        ssum += e;
    }
    #pragma unroll
    for (int o = 16; o; o >>= 1) ssum += __shfl_xor_sync(0xffffffffu, ssum, o);
    if (lane == 0) inv_s[warp] = 1.0f / ssum;
    __syncthreads();

    // V pass: 64-thread group per query pair; d = tid&63
    int dcol = tid & 63;
    #pragma unroll
    for (int qi = (tid >> 6); qi < 4; qi += 2) {
        int sqq = s0 + qi;
        int jq0 = sqq - win + 1; if (jq0 < 0) jq0 = 0;
        int cq = sqq + 1 - jq0;
        const float* vb = base + (size_t)jq0 * (3 * DD) + 2 * DD + h * 64 + dcol;
        float a = 0.f;
        for (int i = 0; i < cq; i++)
            a += sc[qi][i] * vb[(size_t)i * (3 * DD)];
        float v = a * inv_s[qi];
        size_t n = (size_t)(b * SS + sqq);
        split2(v, &out2[n * 2 * DD + h * 64 + dcol],
                  &out2[n * 2 * DD + DD + h * 64 + dcol]);
    }
}

// ---------------------------------------------------------------------------
// (residual) + LayerNorm; optional fp32 / bf16-split / fp16 outputs
// ---------------------------------------------------------------------------
__global__ __launch_bounds__(128) void ln_kernel(
    const float* __restrict__ xin, const float* __restrict__ res,
    const float* __restrict__ g, const float* __restrict__ b,
    float* __restrict__ out, __nv_bfloat16* __restrict__ out2,
    __half* __restrict__ outh)
{
    int row = blockIdx.x;
    const float* xr = xin + (size_t)row * DD;
    const float* rr = res ? res + (size_t)row * DD : nullptr;
    int tid = threadIdx.x;
    float v[4];
    float s = 0.f, s2 = 0.f;
    #pragma unroll
    for (int k = 0; k < 4; k++) {
        int d = tid + k * 128;
        float t = xr[d];
        if (rr) t += rr[d];
        v[k] = t; s += t; s2 += t * t;
    }
    __shared__ float sh[2][4];
    #pragma unroll
    for (int o = 16; o; o >>= 1) {
        s  += __shfl_xor_sync(0xffffffffu, s, o);
        s2 += __shfl_xor_sync(0xffffffffu, s2, o);
    }
    if ((tid & 31) == 0) { sh[0][tid >> 5] = s; sh[1][tid >> 5] = s2; }
    __syncthreads();
    s  = sh[0][0] + sh[0][1] + sh[0][2] + sh[0][3];
    s2 = sh[1][0] + sh[1][1] + sh[1][2] + sh[1][3];
    float mean = s * (1.0f / 512.0f);
    float var = s2 * (1.0f / 512.0f) - mean * mean;
    float rstd = rsqrtf(var + 1e-5f);
    #pragma unroll
    for (int k = 0; k < 4; k++) {
        int d = tid + k * 128;
        float o = (v[k] - mean) * rstd * g[d] + b[d];
        if (out) out[(size_t)row * DD + d] = o;
        if (out2) split2(o, &out2[(size_t)row * 2 * DD + d],
                            &out2[(size_t)row * 2 * DD + DD + d]);
        if (outh) outh[(size_t)row * DD + d] = __float2half_rn(o);
    }
}

// ---------------------------------------------------------------------------
// SwiGLU -> bf16 split directly
// ---------------------------------------------------------------------------
__global__ __launch_bounds__(256) void swiglu_kernel(
    const float* __restrict__ h, __nv_bfloat16* __restrict__ ff2)
{
    int n = blockIdx.x;
    const float* hr = h + (size_t)n * (2 * FFN);
    __nv_bfloat16* fr = ff2 + (size_t)n * (2 * FFN);
    for (int f = threadIdx.x; f < FFN; f += 256) {
        float u = hr[f], gg = hr[FFN + f];
        float v = u * gg / (1.0f + expf(-gg));
        split2(v, &fr[f], &fr[FFN + f]);
    }
}

// ---------------------------------------------------------------------------
// Launch
// ---------------------------------------------------------------------------
#define SMEM_64_128_3 (3 * (2*64*80 + 2*128*80))   // 92160
#define SMEM_LM       (3 * (128*80 + 256*80))      // 92160

extern "C" void kernel_launch(void* const* d_in, const int* in_sizes, int n_in,
                              void* d_out, int out_size)
{
    const int*   ids   = (const int*)  d_in[0];
    const float* emb   = (const float*)d_in[1];
    const float* Wqkv  = (const float*)d_in[2];
    const float* bqkv  = (const float*)d_in[3];
    const float* Wo    = (const float*)d_in[4];
    const float* bo    = (const float*)d_in[5];
    const float* W1    = (const float*)d_in[6];
    const float* b1    = (const float*)d_in[7];
    const float* W2    = (const float*)d_in[8];
    const float* b2    = (const float*)d_in[9];
    const float* ln1_g = (const float*)d_in[10];
    const float* ln1_b = (const float*)d_in[11];
    const float* ln2_g = (const float*)d_in[12];
    const float* ln2_b = (const float*)d_in[13];
    const float* lnf_g = (const float*)d_in[14];
    const float* lnf_b = (const float*)d_in[15];
    float* out = (float*)d_out;

    float *X, *QKV, *TMP, *HB;
    __nv_bfloat16 *wqkv2, *wo2, *w12, *w22, *x2, *att2, *ff2;
    __half *embh, *lnfh;
    cudaGetSymbolAddress((void**)&X,    g_X);
    cudaGetSymbolAddress((void**)&QKV,  g_QKV);
    cudaGetSymbolAddress((void**)&TMP,  g_TMP);
    cudaGetSymbolAddress((void**)&HB,   g_HB);
    cudaGetSymbolAddress((void**)&wqkv2,g_wqkv2);
    cudaGetSymbolAddress((void**)&wo2,  g_wo2);
    cudaGetSymbolAddress((void**)&w12,  g_w12);
    cudaGetSymbolAddress((void**)&w22,  g_w22);
    cudaGetSymbolAddress((void**)&x2,   g_x2);
    cudaGetSymbolAddress((void**)&att2, g_att2);
    cudaGetSymbolAddress((void**)&ff2,  g_ff2);
    cudaGetSymbolAddress((void**)&embh, g_embh);
    cudaGetSymbolAddress((void**)&lnfh, g_lnfh);

    cudaFuncSetAttribute((const void*)gemm_mma<64,128,3,2>,
                         cudaFuncAttributeMaxDynamicSharedMemorySize, SMEM_64_128_3);
    cudaFuncSetAttribute((const void*)gemm_mma<128,256,1,1>,
                         cudaFuncAttributeMaxDynamicSharedMemorySize, SMEM_LM);

    // weight preprocessing (graph-replayed each call)
    prep_split<<<RQKV + RWO + RW1 + RW2, 256>>>(Wqkv, Wo, W1, W2,
                                                wqkv2, wo2, w12, w22);
    cvt_half_kernel<<<(VV * DD) / 1024, 256>>>(emb, embh, VV * DD);

    embed_kernel<<<NT, 128>>>(ids, emb, X, x2);

    for (int l = 0; l < LL; l++) {
        // QKV: [2048,512] x [1536,512]^T   (64x128, 384 blocks, 2 CTA/SM)
        gemm_mma<64,128,3,2><<<dim3(12, 32), 256, SMEM_64_128_3>>>(
            x2, wqkv2 + (size_t)l * 3 * DD * 2 * DD,
            bqkv + (size_t)l * 3 * DD, QKV, 3 * DD, DD);
        // windowed attention -> att2 (bf16 split)
        attn_kernel<<<dim3(SS / 4, HH, BB), 128>>>(QKV, att2);
        // Wo: [2048,512] x [512,512]^T   (64x128, 128 blocks)
        gemm_mma<64,128,3,2><<<dim3(4, 32), 256, SMEM_64_128_3>>>(
            att2, wo2 + (size_t)l * DD * 2 * DD,
            bo + (size_t)l * DD, TMP, DD, DD);
        // x = LN(x + attn_out)
        ln_kernel<<<NT, 128>>>(X, TMP, ln1_g + (size_t)l * DD,
                               ln1_b + (size_t)l * DD, X, x2, nullptr);
        // W1: [2048,512] x [4096,512]^T   (64x128, 1024 blocks, 2 CTA/SM)
        gemm_mma<64,128,3,2><<<dim3(32, 32), 256, SMEM_64_128_3>>>(
            x2, w12 + (size_t)l * 2 * FFN * 2 * DD,
            b1 + (size_t)l * 2 * FFN, HB, 2 * FFN, DD);
        swiglu_kernel<<<NT, 256>>>(HB, ff2);
        // W2: [2048,2048] x [512,2048]^T  (64x128, 128 blocks)
        gemm_mma<64,128,3,2><<<dim3(4, 32), 256, SMEM_64_128_3>>>(
            ff2, w22 + (size_t)l * DD * 2 * FFN,
            b2 + (size_t)l * DD, TMP, DD, FFN);
        // x = LN(x + ff_out)
        ln_kernel<<<NT, 128>>>(X, TMP, ln2_g + (size_t)l * DD,
                               ln2_b + (size_t)l * DD, X, x2, nullptr);
    }

    // final LN -> fp16, tied LM head (fp16 single-pass, 128x256, 2000 blocks)
    ln_kernel<<<NT, 128>>>(X, nullptr, lnf_g, lnf_b, nullptr, nullptr, lnfh);
    gemm_mma<128,256,1,1><<<dim3(VV / 256, NT / 128), 256, SMEM_LM>>>(
        (const __nv_bfloat16*)lnfh, (const __nv_bfloat16*)embh,
        nullptr, out, VV, DD);
}

// round 8
// speedup vs baseline: 1.5306x; 1.0049x over previous
#include <cuda_runtime.h>
#include <cuda_bf16.h>
#include <cuda_fp16.h>
#include <stdint.h>
#include <math.h>

// Problem constants
#define BB 2
#define SS 1024
#define DD 512
#define HH 8
#define LL 6
#define VV 32000
#define FFN 2048
#define NT (BB*SS)          // 2048 tokens

// ---------------------------------------------------------------------------
// Device scratch (static, no allocations)
// ---------------------------------------------------------------------------
__device__ float g_X  [NT*DD];
__device__ float g_QKV[NT*3*DD];
__device__ float g_TMP[NT*DD];
__device__ float g_HB [NT*2*FFN];
__device__ float g_PART[4*NT*DD];                         // split-K partials

__device__ __nv_bfloat16 g_wqkv2[(size_t)LL*3*DD*2*DD];   // [rows, 2K] hi|lo
__device__ __nv_bfloat16 g_wo2  [(size_t)LL*DD*2*DD];
__device__ __nv_bfloat16 g_w12  [(size_t)LL*2*FFN*2*DD];
__device__ __nv_bfloat16 g_w22  [(size_t)LL*DD*2*FFN];
__device__ __nv_bfloat16 g_x2   [(size_t)NT*2*DD];
__device__ __nv_bfloat16 g_att2 [(size_t)NT*2*DD];
__device__ __nv_bfloat16 g_ff2  [(size_t)NT*2*FFN];
__device__ __half        g_embh [(size_t)VV*DD];          // fp16 for LM head
__device__ __half        g_lnfh [(size_t)NT*DD];

// ---------------------------------------------------------------------------
// PTX helpers (baseline ISA only: cp.async, ldmatrix, mma.sync)
// ---------------------------------------------------------------------------
__device__ __forceinline__ uint32_t smem_to_u32(const void* p) {
    uint32_t a;
    asm("{ .reg .u64 t; cvta.to.shared.u64 t, %1; cvt.u32.u64 %0, t; }"
        : "=r"(a) : "l"(p));
    return a;
}
__device__ __forceinline__ void cp16(uint32_t dst, const void* src) {
    asm volatile("cp.async.cg.shared.global [%0], [%1], 16;\n" :: "r"(dst), "l"(src) : "memory");
}
#define CP_COMMIT()  asm volatile("cp.async.commit_group;" ::: "memory")
#define CP_WAIT1()   asm volatile("cp.async.wait_group 1;" ::: "memory")

__device__ __forceinline__ void ldm_x4(uint32_t* r, uint32_t addr) {
    asm volatile("ldmatrix.sync.aligned.m8n8.x4.shared.b16 {%0,%1,%2,%3}, [%4];"
        : "=r"(r[0]), "=r"(r[1]), "=r"(r[2]), "=r"(r[3]) : "r"(addr));
}
template<bool F16>
__device__ __forceinline__ void mma16816(float* c, const uint32_t* a,
                                         uint32_t b0, uint32_t b1) {
    if (F16)
        asm volatile(
            "mma.sync.aligned.m16n8k16.row.col.f32.f16.f16.f32 "
            "{%0,%1,%2,%3}, {%4,%5,%6,%7}, {%8,%9}, {%0,%1,%2,%3};"
            : "+f"(c[0]), "+f"(c[1]), "+f"(c[2]), "+f"(c[3])
            : "r"(a[0]), "r"(a[1]), "r"(a[2]), "r"(a[3]), "r"(b0), "r"(b1));
    else
        asm volatile(
            "mma.sync.aligned.m16n8k16.row.col.f32.bf16.bf16.f32 "
            "{%0,%1,%2,%3}, {%4,%5,%6,%7}, {%8,%9}, {%0,%1,%2,%3};"
            : "+f"(c[0]), "+f"(c[1]), "+f"(c[2]), "+f"(c[3])
            : "r"(a[0]), "r"(a[1]), "r"(a[2]), "r"(a[3]), "r"(b0), "r"(b1));
}

// ---------------------------------------------------------------------------
// bf16 hi/lo split helpers
// ---------------------------------------------------------------------------
__device__ __forceinline__ void split2(float x, __nv_bfloat16* hi_p, __nv_bfloat16* lo_p) {
    __nv_bfloat16 h = __float2bfloat16_rn(x);
    *hi_p = h;
    *lo_p = __float2bfloat16_rn(x - __bfloat162float(h));
}

// Fused weight split: all 4 weight tensors in one launch.
#define RQKV (LL*3*DD)
#define RWO  (LL*DD)
#define RW1  (LL*2*FFN)
#define RW2  (LL*DD)
__global__ __launch_bounds__(256) void prep_split(
    const float* __restrict__ Wqkv, const float* __restrict__ Wo,
    const float* __restrict__ W1,   const float* __restrict__ W2,
    __nv_bfloat16* __restrict__ wqkv2, __nv_bfloat16* __restrict__ wo2,
    __nv_bfloat16* __restrict__ w12,   __nv_bfloat16* __restrict__ w22)
{
    int r = blockIdx.x;
    const float* s; __nv_bfloat16* d; int K;
    if (r < RQKV)                    { s = Wqkv + (size_t)r * DD; d = wqkv2 + (size_t)r * 2 * DD; K = DD; }
    else if (r < RQKV + RWO)         { r -= RQKV; s = Wo + (size_t)r * DD; d = wo2 + (size_t)r * 2 * DD; K = DD; }
    else if (r < RQKV + RWO + RW1)   { r -= RQKV + RWO; s = W1 + (size_t)r * DD; d = w12 + (size_t)r * 2 * DD; K = DD; }
    else                             { r -= RQKV + RWO + RW1; s = W2 + (size_t)r * FFN; d = w22 + (size_t)r * 2 * FFN; K = FFN; }
    for (int c = threadIdx.x; c < K; c += 256)
        split2(s[c], &d[c], &d[K + c]);
}

// fp32 -> fp16 plain convert
__global__ __launch_bounds__(256) void cvt_half_kernel(
    const float* __restrict__ s, __half* __restrict__ d, int n)
{
    int i = (blockIdx.x * 256 + threadIdx.x) * 4;
    if (i < n) {
        float4 v = *(const float4*)(s + i);
        d[i + 0] = __float2half_rn(v.x);
        d[i + 1] = __float2half_rn(v.y);
        d[i + 2] = __float2half_rn(v.z);
        d[i + 3] = __float2half_rn(v.w);
    }
}

// ---------------------------------------------------------------------------
// Split-K reduce: C = sum_s P[s] + bias   (fixed order -> deterministic)
// ---------------------------------------------------------------------------
template<int S>
__global__ __launch_bounds__(256) void reduce_k(
    const float* __restrict__ P, const float* __restrict__ bias,
    float* __restrict__ C, int MN, int N)
{
    int i = (blockIdx.x * 256 + threadIdx.x) * 4;
    if (i >= MN) return;
    float4 a = *(const float4*)(P + i);
    #pragma unroll
    for (int s = 1; s < S; s++) {
        float4 b = *(const float4*)(P + (size_t)s * MN + i);
        a.x += b.x; a.y += b.y; a.z += b.z; a.w += b.w;
    }
    float4 bb = *(const float4*)(bias + (i % N));
    a.x += bb.x; a.y += bb.y; a.z += bb.z; a.w += bb.w;
    *(float4*)(C + i) = a;
}

// ---------------------------------------------------------------------------
// Tensor-core GEMM with optional split-K (blockIdx.z = split index).
// C[M,N] = A * B^T (+ bias when not split).
// PASSES=3 (bf16x3): A2,B2 = [rows, 2K] bf16 hi|lo; hi*hi + hi*lo + lo*hi.
// PASSES=1 (fp16):   A2,B2 = [rows, K] fp16, single pass.
// 256 threads (8 warps, 2m x 4n), warp tile (TM/2) x (TN/4), K-chunk 32,
// 3-buffer cp.async pipeline, lookahead 2. smem row pitch 80B.
// MINB=2 caps regs at 128 for 2 CTAs/SM.
// ---------------------------------------------------------------------------
template<int TM, int TN, int PASSES, int MINB>
__global__ __launch_bounds__(256, MINB)
void gemm_mma(const __nv_bfloat16* __restrict__ A2,
              const __nv_bfloat16* __restrict__ B2,
              const float* __restrict__ bias,
              float* __restrict__ C, int N, int K, int Ks, size_t partStride)
{
    constexpr bool F16 = (PASSES == 1);
    constexpr int WM = TM / 2, WN = TN / 4;
    constexpr int MI = WM / 16;
    constexpr int NI = WN / 8;
    constexpr int NB = WN / 16;
    constexpr int AT = (PASSES == 3) ? 2 : 1;
    constexpr int SA = AT * TM * 80;
    constexpr int SB = AT * TN * 80;
    constexpr int STAGE = SA + SB;
    constexpr int ACH = AT * TM * 4;
    constexpr int NCH = ACH + AT * TN * 4;

    extern __shared__ __align__(128) char dsm[];
    uint32_t sbase = smem_to_u32(dsm);

    int tid = threadIdx.x, lane = tid & 31, warp = tid >> 5;
    int wm = warp >> 2, wn = warp & 3;
    size_t bm = (size_t)blockIdx.y * TM;
    size_t bn = (size_t)blockIdx.x * TN;
    int kOff = blockIdx.z * Ks;
    C += (size_t)blockIdx.z * partStride;
    int astr = (PASSES == 3) ? 2 * K : K;
    int nk = Ks / 32;

    float acc[MI][NI][4];
    #pragma unroll
    for (int mi = 0; mi < MI; mi++)
        #pragma unroll
        for (int ni = 0; ni < NI; ni++)
            #pragma unroll
            for (int j = 0; j < 4; j++) acc[mi][ni][j] = 0.f;

    auto load_stage = [&](int it) {
        int buf = it % 3;
        int kc = kOff + it * 32;
        uint32_t sAp = sbase + buf * STAGE;
        uint32_t sBp = sAp + SA;
        #pragma unroll
        for (int ii = 0; ii < NCH / 256; ii++) {
            int i = tid + ii * 256;
            if (i < ACH) {
                int row, half, seg;
                if (PASSES == 3) { row = i >> 3; half = (i >> 2) & 1; seg = i & 3; }
                else             { row = i >> 2; half = 0;            seg = i & 3; }
                cp16(sAp + (uint32_t)(half * (TM * 80) + row * 80 + seg * 16),
                     A2 + (bm + row) * (size_t)astr + half * K + kc + seg * 8);
            } else {
                int j = i - ACH;
                int row, half, seg;
                if (PASSES == 3) { row = j >> 3; half = (j >> 2) & 1; seg = j & 3; }
                else             { row = j >> 2; half = 0;            seg = j & 3; }
                cp16(sBp + (uint32_t)(half * (TN * 80) + row * 80 + seg * 16),
                     B2 + (bn + row) * (size_t)astr + half * K + kc + seg * 8);
            }
        }
    };

    load_stage(0); CP_COMMIT();
    if (nk > 1) load_stage(1);
    CP_COMMIT();

    for (int it = 0; it < nk; it++) {
        CP_WAIT1();
        __syncthreads();
        if (it + 2 < nk) load_stage(it + 2);
        CP_COMMIT();

        int buf = it % 3;
        uint32_t sAhi = sbase + buf * STAGE;
        uint32_t sAlo = sAhi + TM * 80;
        uint32_t sBhi = sAhi + SA;
        uint32_t sBlo = sBhi + TN * 80;

        #pragma unroll
        for (int ks = 0; ks < 2; ks++) {
            int arow = wm * WM + (lane & 15);
            int achk = ks * 2 + (lane >> 4);
            uint32_t aoff = (uint32_t)(arow * 80 + achk * 16);
            int sel = lane >> 3, within = lane & 7;
            int nrow = wn * WN + within + ((sel >> 1) << 3);
            int bchk = ks * 2 + (sel & 1);
            uint32_t boff = (uint32_t)(nrow * 80 + bchk * 16);

            uint32_t ahf[MI][4], bhf[NB][4];
            #pragma unroll
            for (int mi = 0; mi < MI; mi++)
                ldm_x4(ahf[mi], sAhi + aoff + mi * 16 * 80);
            #pragma unroll
            for (int n2 = 0; n2 < NB; n2++)
                ldm_x4(bhf[n2], sBhi + boff + n2 * 16 * 80);

            // pass 0: hi * hi
            #pragma unroll
            for (int mi = 0; mi < MI; mi++)
                #pragma unroll
                for (int ni = 0; ni < NI; ni++)
                    mma16816<F16>(acc[mi][ni], ahf[mi],
                                  bhf[ni >> 1][(ni & 1) * 2],
                                  bhf[ni >> 1][(ni & 1) * 2 + 1]);
            if (PASSES == 3) {
                uint32_t blf[NB][4];
                #pragma unroll
                for (int n2 = 0; n2 < NB; n2++)
                    ldm_x4(blf[n2], sBlo + boff + n2 * 16 * 80);
                // pass 1: Ahi * Blo
                #pragma unroll
                for (int mi = 0; mi < MI; mi++)
                    #pragma unroll
                    for (int ni = 0; ni < NI; ni++)
                        mma16816<F16>(acc[mi][ni], ahf[mi],
                                      blf[ni >> 1][(ni & 1) * 2],
                                      blf[ni >> 1][(ni & 1) * 2 + 1]);
                uint32_t alf[MI][4];
                #pragma unroll
                for (int mi = 0; mi < MI; mi++)
                    ldm_x4(alf[mi], sAlo + aoff + mi * 16 * 80);
                // pass 2: Alo * Bhi
                #pragma unroll
                for (int mi = 0; mi < MI; mi++)
                    #pragma unroll
                    for (int ni = 0; ni < NI; ni++)
                        mma16816<F16>(acc[mi][ni], alf[mi],
                                      bhf[ni >> 1][(ni & 1) * 2],
                                      bhf[ni >> 1][(ni & 1) * 2 + 1]);
            }
        }
    }

    // epilogue
    int r0 = (int)bm + wm * WM + (lane >> 2);
    int c0 = (int)bn + wn * WN + (lane & 3) * 2;
    #pragma unroll
    for (int mi = 0; mi < MI; mi++) {
        #pragma unroll
        for (int ni = 0; ni < NI; ni++) {
            int row = r0 + mi * 16;
            int col = c0 + ni * 8;
            float bx = 0.f, by = 0.f;
            if (bias) { bx = bias[col]; by = bias[col + 1]; }
            float2 lo, hi;
            lo.x = acc[mi][ni][0] + bx; lo.y = acc[mi][ni][1] + by;
            hi.x = acc[mi][ni][2] + bx; hi.y = acc[mi][ni][3] + by;
            *(float2*)(C + (size_t)row * N + col) = lo;
            *(float2*)(C + (size_t)(row + 8) * N + col) = hi;
        }
    }
}

// ---------------------------------------------------------------------------
// Embedding + positional encoding -> X fp32 and X2 bf16 split
// ---------------------------------------------------------------------------
__global__ __launch_bounds__(128) void embed_kernel(
    const int* __restrict__ ids, const float* __restrict__ emb,
    float* __restrict__ x, __nv_bfloat16* __restrict__ x2)
{
    int n = blockIdx.x;
    int s = n & (SS - 1);
    int id = ids[n];
    const float Cc = -0.01798894591761708f;  // -ln(10000)/512
    #pragma unroll
    for (int k = 0; k < 4; k++) {
        int d = threadIdx.x + k * 128;
        float ang = (float)s * expf((float)(d & ~1) * Cc);
        float pe = (d & 1) ? cosf(ang) : sinf(ang);
        float v = emb[(size_t)id * DD + d] + pe;
        x[(size_t)n * DD + d] = v;
        split2(v, &x2[(size_t)n * 2 * DD + d], &x2[(size_t)n * 2 * DD + DD + d]);
    }
}

// ---------------------------------------------------------------------------
// Windowed attention: 4 queries/block, warp-per-query. Output: bf16 split.
// ---------------------------------------------------------------------------
__global__ __launch_bounds__(128) void attn_kernel(
    const float* __restrict__ qkv, __nv_bfloat16* __restrict__ out2)
{
    int s0 = blockIdx.x * 4, h = blockIdx.y, b = blockIdx.z;
    int win = (h + 1) * 64;
    int tid = threadIdx.x, lane = tid & 31, warp = tid >> 5;

    __shared__ float sc[4][512];
    __shared__ float inv_s[4];

    const float* base = qkv + (size_t)b * SS * (3 * DD);

    int sq = s0 + warp;
    int j0 = sq - win + 1; if (j0 < 0) j0 = 0;
    int cnt = sq + 1 - j0;

    float2 qq = *(const float2*)(base + (size_t)sq * (3 * DD) + h * 64 + lane * 2);

    float m = -3.4e38f;
    for (int i = 0; i < cnt; i++) {
        const float* kp = base + (size_t)(j0 + i) * (3 * DD) + DD + h * 64;
        float2 kk = *(const float2*)(kp + lane * 2);
        float d = kk.x * qq.x + kk.y * qq.y;
        #pragma unroll
        for (int o = 16; o; o >>= 1) d += __shfl_xor_sync(0xffffffffu, d, o);
        d *= 0.125f;                              // 1/sqrt(64)
        if (lane == 0) sc[warp][i] = d;
        m = fmaxf(m, d);
    }
    __syncwarp();
    float ssum = 0.f;
    for (int i = lane; i < cnt; i += 32) {
        float e = expf(sc[warp][i] - m);
        sc[warp][i] = e;
        ssum += e;
    }
    #pragma unroll
    for (int o = 16; o; o >>= 1) ssum += __shfl_xor_sync(0xffffffffu, ssum, o);
    if (lane == 0) inv_s[warp] = 1.0f / ssum;
    __syncthreads();

    // V pass: 64-thread group per query pair; d = tid&63
    int dcol = tid & 63;
    #pragma unroll
    for (int qi = (tid >> 6); qi < 4; qi += 2) {
        int sqq = s0 + qi;
        int jq0 = sqq - win + 1; if (jq0 < 0) jq0 = 0;
        int cq = sqq + 1 - jq0;
        const float* vb = base + (size_t)jq0 * (3 * DD) + 2 * DD + h * 64 + dcol;
        float a = 0.f;
        for (int i = 0; i < cq; i++)
            a += sc[qi][i] * vb[(size_t)i * (3 * DD)];
        float v = a * inv_s[qi];
        size_t n = (size_t)(b * SS + sqq);
        split2(v, &out2[n * 2 * DD + h * 64 + dcol],
                  &out2[n * 2 * DD + DD + h * 64 + dcol]);
    }
}

// ---------------------------------------------------------------------------
// (residual) + LayerNorm; optional fp32 / bf16-split / fp16 outputs
// ---------------------------------------------------------------------------
__global__ __launch_bounds__(128) void ln_kernel(
    const float* __restrict__ xin, const float* __restrict__ res,
    const float* __restrict__ g, const float* __restrict__ b,
    float* __restrict__ out, __nv_bfloat16* __restrict__ out2,
    __half* __restrict__ outh)
{
    int row = blockIdx.x;
    const float* xr = xin + (size_t)row * DD;
    const float* rr = res ? res + (size_t)row * DD : nullptr;
    int tid = threadIdx.x;
    float v[4];
    float s = 0.f, s2 = 0.f;
    #pragma unroll
    for (int k = 0; k < 4; k++) {
        int d = tid + k * 128;
        float t = xr[d];
        if (rr) t += rr[d];
        v[k] = t; s += t; s2 += t * t;
    }
    __shared__ float sh[2][4];
    #pragma unroll
    for (int o = 16; o; o >>= 1) {
        s  += __shfl_xor_sync(0xffffffffu, s, o);
        s2 += __shfl_xor_sync(0xffffffffu, s2, o);
    }
    if ((tid & 31) == 0) { sh[0][tid >> 5] = s; sh[1][tid >> 5] = s2; }
    __syncthreads();
    s  = sh[0][0] + sh[0][1] + sh[0][2] + sh[0][3];
    s2 = sh[1][0] + sh[1][1] + sh[1][2] + sh[1][3];
    float mean = s * (1.0f / 512.0f);
    float var = s2 * (1.0f / 512.0f) - mean * mean;
    float rstd = rsqrtf(var + 1e-5f);
    #pragma unroll
    for (int k = 0; k < 4; k++) {
        int d = tid + k * 128;
        float o = (v[k] - mean) * rstd * g[d] + b[d];
        if (out) out[(size_t)row * DD + d] = o;
        if (out2) split2(o, &out2[(size_t)row * 2 * DD + d],
                            &out2[(size_t)row * 2 * DD + DD + d]);
        if (outh) outh[(size_t)row * DD + d] = __float2half_rn(o);
    }
}

// ---------------------------------------------------------------------------
// SwiGLU -> bf16 split directly
// ---------------------------------------------------------------------------
__global__ __launch_bounds__(256) void swiglu_kernel(
    const float* __restrict__ h, __nv_bfloat16* __restrict__ ff2)
{
    int n = blockIdx.x;
    const float* hr = h + (size_t)n * (2 * FFN);
    __nv_bfloat16* fr = ff2 + (size_t)n * (2 * FFN);
    for (int f = threadIdx.x; f < FFN; f += 256) {
        float u = hr[f], gg = hr[FFN + f];
        float v = u * gg / (1.0f + expf(-gg));
        split2(v, &fr[f], &fr[FFN + f]);
    }
}

// ---------------------------------------------------------------------------
// Launch
// ---------------------------------------------------------------------------
#define SMEM_64_128_3 (3 * (2*64*80 + 2*128*80))   // 92160
#define SMEM_LM       (3 * (128*80 + 256*80))      // 92160

extern "C" void kernel_launch(void* const* d_in, const int* in_sizes, int n_in,
                              void* d_out, int out_size)
{
    const int*   ids   = (const int*)  d_in[0];
    const float* emb   = (const float*)d_in[1];
    const float* Wqkv  = (const float*)d_in[2];
    const float* bqkv  = (const float*)d_in[3];
    const float* Wo    = (const float*)d_in[4];
    const float* bo    = (const float*)d_in[5];
    const float* W1    = (const float*)d_in[6];
    const float* b1    = (const float*)d_in[7];
    const float* W2    = (const float*)d_in[8];
    const float* b2    = (const float*)d_in[9];
    const float* ln1_g = (const float*)d_in[10];
    const float* ln1_b = (const float*)d_in[11];
    const float* ln2_g = (const float*)d_in[12];
    const float* ln2_b = (const float*)d_in[13];
    const float* lnf_g = (const float*)d_in[14];
    const float* lnf_b = (const float*)d_in[15];
    float* out = (float*)d_out;

    float *X, *QKV, *TMP, *HB, *PART;
    __nv_bfloat16 *wqkv2, *wo2, *w12, *w22, *x2, *att2, *ff2;
    __half *embh, *lnfh;
    cudaGetSymbolAddress((void**)&X,    g_X);
    cudaGetSymbolAddress((void**)&QKV,  g_QKV);
    cudaGetSymbolAddress((void**)&TMP,  g_TMP);
    cudaGetSymbolAddress((void**)&HB,   g_HB);
    cudaGetSymbolAddress((void**)&PART, g_PART);
    cudaGetSymbolAddress((void**)&wqkv2,g_wqkv2);
    cudaGetSymbolAddress((void**)&wo2,  g_wo2);
    cudaGetSymbolAddress((void**)&w12,  g_w12);
    cudaGetSymbolAddress((void**)&w22,  g_w22);
    cudaGetSymbolAddress((void**)&x2,   g_x2);
    cudaGetSymbolAddress((void**)&att2, g_att2);
    cudaGetSymbolAddress((void**)&ff2,  g_ff2);
    cudaGetSymbolAddress((void**)&embh, g_embh);
    cudaGetSymbolAddress((void**)&lnfh, g_lnfh);

    cudaFuncSetAttribute((const void*)gemm_mma<64,128,3,2>,
                         cudaFuncAttributeMaxDynamicSharedMemorySize, SMEM_64_128_3);
    cudaFuncSetAttribute((const void*)gemm_mma<128,256,1,1>,
                         cudaFuncAttributeMaxDynamicSharedMemorySize, SMEM_LM);

    // weight preprocessing (graph-replayed each call)
    prep_split<<<RQKV + RWO + RW1 + RW2, 256>>>(Wqkv, Wo, W1, W2,
                                                wqkv2, wo2, w12, w22);
    cvt_half_kernel<<<(VV * DD) / 1024, 256>>>(emb, embh, VV * DD);

    embed_kernel<<<NT, 128>>>(ids, emb, X, x2);

    const int MN = NT * DD;
    for (int l = 0; l < LL; l++) {
        // QKV: [2048,512] x [1536,512]^T   (64x128, 384 blocks, 2 CTA/SM)
        gemm_mma<64,128,3,2><<<dim3(12, 32), 256, SMEM_64_128_3>>>(
            x2, wqkv2 + (size_t)l * 3 * DD * 2 * DD,
            bqkv + (size_t)l * 3 * DD, QKV, 3 * DD, DD, DD, 0);
        // windowed attention -> att2 (bf16 split)
        attn_kernel<<<dim3(SS / 4, HH, BB), 128>>>(QKV, att2);
        // Wo: [2048,512] x [512,512]^T   split-K=2 -> 256 blocks
        gemm_mma<64,128,3,2><<<dim3(4, 32, 2), 256, SMEM_64_128_3>>>(
            att2, wo2 + (size_t)l * DD * 2 * DD,
            nullptr, PART, DD, DD, DD / 2, (size_t)MN);
        reduce_k<2><<<MN / 1024, 256>>>(PART, bo + (size_t)l * DD, TMP, MN, DD);
        // x = LN(x + attn_out)
        ln_kernel<<<NT, 128>>>(X, TMP, ln1_g + (size_t)l * DD,
                               ln1_b + (size_t)l * DD, X, x2, nullptr);
        // W1: [2048,512] x [4096,512]^T   (64x128, 1024 blocks, 2 CTA/SM)
        gemm_mma<64,128,3,2><<<dim3(32, 32), 256, SMEM_64_128_3>>>(
            x2, w12 + (size_t)l * 2 * FFN * 2 * DD,
            b1 + (size_t)l * 2 * FFN, HB, 2 * FFN, DD, DD, 0);
        swiglu_kernel<<<NT, 256>>>(HB, ff2);
        // W2: [2048,2048] x [512,2048]^T  split-K=4 -> 512 blocks
        gemm_mma<64,128,3,2><<<dim3(4, 32, 4), 256, SMEM_64_128_3>>>(
            ff2, w22 + (size_t)l * DD * 2 * FFN,
            nullptr, PART, DD, FFN, FFN / 4, (size_t)MN);
        reduce_k<4><<<MN / 1024, 256>>>(PART, b2 + (size_t)l * DD, TMP, MN, DD);
        // x = LN(x + ff_out)
        ln_kernel<<<NT, 128>>>(X, TMP, ln2_g + (size_t)l * DD,
                               ln2_b + (size_t)l * DD, X, x2, nullptr);
    }

    // final LN -> fp16, tied LM head (fp16 single-pass, 128x256, 2000 blocks)
    ln_kernel<<<NT, 128>>>(X, nullptr, lnf_g, lnf_b, nullptr, nullptr, lnfh);
    gemm_mma<128,256,1,1><<<dim3(VV / 256, NT / 128), 256, SMEM_LM>>>(
        (const __nv_bfloat16*)lnfh, (const __nv_bfloat16*)embh,
        nullptr, out, VV, DD, DD, 0);
}

// round 10
// speedup vs baseline: 1.7340x; 1.1329x over previous
#include <cuda_runtime.h>
#include <cuda_bf16.h>
#include <cuda_fp16.h>
#include <stdint.h>
#include <math.h>

// Problem constants
#define BB 2
#define SS 1024
#define DD 512
#define HH 8
#define LL 6
#define VV 32000
#define FFN 2048
#define NT (BB*SS)          // 2048 tokens
#define MNtok (NT*DD)

// ---------------------------------------------------------------------------
// Device scratch (static, no allocations)
// ---------------------------------------------------------------------------
__device__ float g_X  [NT*DD];
__device__ float g_QKV[NT*3*DD];
__device__ float g_HB [NT*2*FFN];
__device__ float g_PART[4*NT*DD];                         // split-K partials

__device__ __nv_bfloat16 g_wqkv2[(size_t)LL*3*DD*2*DD];   // [rows, 2K] hi|lo
__device__ __nv_bfloat16 g_wo2  [(size_t)LL*DD*2*DD];
__device__ __nv_bfloat16 g_w12  [(size_t)LL*2*FFN*2*DD];
__device__ __nv_bfloat16 g_w22  [(size_t)LL*DD*2*FFN];
__device__ __nv_bfloat16 g_x2   [(size_t)NT*2*DD];
__device__ __nv_bfloat16 g_att2 [(size_t)NT*2*DD];
__device__ __nv_bfloat16 g_ff2  [(size_t)NT*2*FFN];
__device__ __half        g_embh [(size_t)VV*DD];          // fp16 for LM head
__device__ __half        g_lnfh [(size_t)NT*DD];

// ---------------------------------------------------------------------------
// PTX helpers (baseline ISA only: cp.async, ldmatrix, mma.sync)
// ---------------------------------------------------------------------------
__device__ __forceinline__ uint32_t smem_to_u32(const void* p) {
    uint32_t a;
    asm("{ .reg .u64 t; cvta.to.shared.u64 t, %1; cvt.u32.u64 %0, t; }"
        : "=r"(a) : "l"(p));
    return a;
}
__device__ __forceinline__ void cp16(uint32_t dst, const void* src) {
    asm volatile("cp.async.cg.shared.global [%0], [%1], 16;\n" :: "r"(dst), "l"(src) : "memory");
}
#define CP_COMMIT()  asm volatile("cp.async.commit_group;" ::: "memory")
#define CP_WAIT1()   asm volatile("cp.async.wait_group 1;" ::: "memory")

__device__ __forceinline__ void ldm_x4(uint32_t* r, uint32_t addr) {
    asm volatile("ldmatrix.sync.aligned.m8n8.x4.shared.b16 {%0,%1,%2,%3}, [%4];"
        : "=r"(r[0]), "=r"(r[1]), "=r"(r[2]), "=r"(r[3]) : "r"(addr));
}
template<bool F16>
__device__ __forceinline__ void mma16816(float* c, const uint32_t* a,
                                         uint32_t b0, uint32_t b1) {
    if (F16)
        asm volatile(
            "mma.sync.aligned.m16n8k16.row.col.f32.f16.f16.f32 "
            "{%0,%1,%2,%3}, {%4,%5,%6,%7}, {%8,%9}, {%0,%1,%2,%3};"
            : "+f"(c[0]), "+f"(c[1]), "+f"(c[2]), "+f"(c[3])
            : "r"(a[0]), "r"(a[1]), "r"(a[2]), "r"(a[3]), "r"(b0), "r"(b1));
    else
        asm volatile(
            "mma.sync.aligned.m16n8k16.row.col.f32.bf16.bf16.f32 "
            "{%0,%1,%2,%3}, {%4,%5,%6,%7}, {%8,%9}, {%0,%1,%2,%3};"
            : "+f"(c[0]), "+f"(c[1]), "+f"(c[2]), "+f"(c[3])
            : "r"(a[0]), "r"(a[1]), "r"(a[2]), "r"(a[3]), "r"(b0), "r"(b1));
}

// ---------------------------------------------------------------------------
// bf16 hi/lo split helpers
// ---------------------------------------------------------------------------
__device__ __forceinline__ void split2(float x, __nv_bfloat16* hi_p, __nv_bfloat16* lo_p) {
    __nv_bfloat16 h = __float2bfloat16_rn(x);
    *hi_p = h;
    *lo_p = __float2bfloat16_rn(x - __bfloat162float(h));
}

// Fused weight split: all 4 weight tensors in one launch.
#define RQKV (LL*3*DD)
#define RWO  (LL*DD)
#define RW1  (LL*2*FFN)
#define RW2  (LL*DD)
__global__ __launch_bounds__(256) void prep_split(
    const float* __restrict__ Wqkv, const float* __restrict__ Wo,
    const float* __restrict__ W1,   const float* __restrict__ W2,
    __nv_bfloat16* __restrict__ wqkv2, __nv_bfloat16* __restrict__ wo2,
    __nv_bfloat16* __restrict__ w12,   __nv_bfloat16* __restrict__ w22)
{
    int r = blockIdx.x;
    const float* s; __nv_bfloat16* d; int K;
    if (r < RQKV)                    { s = Wqkv + (size_t)r * DD; d = wqkv2 + (size_t)r * 2 * DD; K = DD; }
    else if (r < RQKV + RWO)         { r -= RQKV; s = Wo + (size_t)r * DD; d = wo2 + (size_t)r * 2 * DD; K = DD; }
    else if (r < RQKV + RWO + RW1)   { r -= RQKV + RWO; s = W1 + (size_t)r * DD; d = w12 + (size_t)r * 2 * DD; K = DD; }
    else                             { r -= RQKV + RWO + RW1; s = W2 + (size_t)r * FFN; d = w22 + (size_t)r * 2 * FFN; K = FFN; }
    for (int c = threadIdx.x; c < K; c += 256)
        split2(s[c], &d[c], &d[K + c]);
}

// fp32 -> fp16 plain convert
__global__ __launch_bounds__(256) void cvt_half_kernel(
    const float* __restrict__ s, __half* __restrict__ d, int n)
{
    int i = (blockIdx.x * 256 + threadIdx.x) * 4;
    if (i < n) {
        float4 v = *(const float4*)(s + i);
        d[i + 0] = __float2half_rn(v.x);
        d[i + 1] = __float2half_rn(v.y);
        d[i + 2] = __float2half_rn(v.z);
        d[i + 3] = __float2half_rn(v.w);
    }
}

// ---------------------------------------------------------------------------
// Tensor-core GEMM with optional split-K (blockIdx.z = split index).
// C[M,N] = A * B^T (+ bias when not split).
// PASSES=3 (bf16x3): A2,B2 = [rows, 2K] bf16 hi|lo; hi*hi + hi*lo + lo*hi.
// PASSES=1 (fp16):   A2,B2 = [rows, K] fp16, single pass.
// 256 threads (8 warps, 2m x 4n), warp tile (TM/2) x (TN/4), K-chunk 32,
// 3-buffer cp.async pipeline, lookahead 2. smem row pitch 80B.
// MINB=2 caps regs at 128 for 2 CTAs/SM.
// ---------------------------------------------------------------------------
template<int TM, int TN, int PASSES, int MINB>
__global__ __launch_bounds__(256, MINB)
void gemm_mma(const __nv_bfloat16* __restrict__ A2,
              const __nv_bfloat16* __restrict__ B2,
              const float* __restrict__ bias,
              float* __restrict__ C, int N, int K, int Ks, size_t partStride)
{
    constexpr bool F16 = (PASSES == 1);
    constexpr int WM = TM / 2, WN = TN / 4;
    constexpr int MI = WM / 16;
    constexpr int NI = WN / 8;
    constexpr int NB = WN / 16;
    constexpr int AT = (PASSES == 3) ? 2 : 1;
    constexpr int SA = AT * TM * 80;
    constexpr int SB = AT * TN * 80;
    constexpr int STAGE = SA + SB;
    constexpr int ACH = AT * TM * 4;
    constexpr int NCH = ACH + AT * TN * 4;

    extern __shared__ __align__(128) char dsm[];
    uint32_t sbase = smem_to_u32(dsm);

    int tid = threadIdx.x, lane = tid & 31, warp = tid >> 5;
    int wm = warp >> 2, wn = warp & 3;
    size_t bm = (size_t)blockIdx.y * TM;
    size_t bn = (size_t)blockIdx.x * TN;
    int kOff = blockIdx.z * Ks;
    C += (size_t)blockIdx.z * partStride;
    int astr = (PASSES == 3) ? 2 * K : K;
    int nk = Ks / 32;

    float acc[MI][NI][4];
    #pragma unroll
    for (int mi = 0; mi < MI; mi++)
        #pragma unroll
        for (int ni = 0; ni < NI; ni++)
            #pragma unroll
            for (int j = 0; j < 4; j++) acc[mi][ni][j] = 0.f;

    auto load_stage = [&](int it) {
        int buf = it % 3;
        int kc = kOff + it * 32;
        uint32_t sAp = sbase + buf * STAGE;
        uint32_t sBp = sAp + SA;
        #pragma unroll
        for (int ii = 0; ii < NCH / 256; ii++) {
            int i = tid + ii * 256;
            if (i < ACH) {
                int row, half, seg;
                if (PASSES == 3) { row = i >> 3; half = (i >> 2) & 1; seg = i & 3; }
                else             { row = i >> 2; half = 0;            seg = i & 3; }
                cp16(sAp + (uint32_t)(half * (TM * 80) + row * 80 + seg * 16),
                     A2 + (bm + row) * (size_t)astr + half * K + kc + seg * 8);
            } else {
                int j = i - ACH;
                int row, half, seg;
                if (PASSES == 3) { row = j >> 3; half = (j >> 2) & 1; seg = j & 3; }
                else             { row = j >> 2; half = 0;            seg = j & 3; }
                cp16(sBp + (uint32_t)(half * (TN * 80) + row * 80 + seg * 16),
                     B2 + (bn + row) * (size_t)astr + half * K + kc + seg * 8);
            }
        }
    };

    load_stage(0); CP_COMMIT();
    if (nk > 1) load_stage(1);
    CP_COMMIT();

    for (int it = 0; it < nk; it++) {
        CP_WAIT1();
        __syncthreads();
        if (it + 2 < nk) load_stage(it + 2);
        CP_COMMIT();

        int buf = it % 3;
        uint32_t sAhi = sbase + buf * STAGE;
        uint32_t sAlo = sAhi + TM * 80;
        uint32_t sBhi = sAhi + SA;
        uint32_t sBlo = sBhi + TN * 80;

        #pragma unroll
        for (int ks = 0; ks < 2; ks++) {
            int arow = wm * WM + (lane & 15);
            int achk = ks * 2 + (lane >> 4);
            uint32_t aoff = (uint32_t)(arow * 80 + achk * 16);
            int sel = lane >> 3, within = lane & 7;
            int nrow = wn * WN + within + ((sel >> 1) << 3);
            int bchk = ks * 2 + (sel & 1);
            uint32_t boff = (uint32_t)(nrow * 80 + bchk * 16);

            uint32_t ahf[MI][4], bhf[NB][4];
            #pragma unroll
            for (int mi = 0; mi < MI; mi++)
                ldm_x4(ahf[mi], sAhi + aoff + mi * 16 * 80);
            #pragma unroll
            for (int n2 = 0; n2 < NB; n2++)
                ldm_x4(bhf[n2], sBhi + boff + n2 * 16 * 80);

            // pass 0: hi * hi
            #pragma unroll
            for (int mi = 0; mi < MI; mi++)
                #pragma unroll
                for (int ni = 0; ni < NI; ni++)
                    mma16816<F16>(acc[mi][ni], ahf[mi],
                                  bhf[ni >> 1][(ni & 1) * 2],
                                  bhf[ni >> 1][(ni & 1) * 2 + 1]);
            if (PASSES == 3) {
                uint32_t blf[NB][4];
                #pragma unroll
                for (int n2 = 0; n2 < NB; n2++)
                    ldm_x4(blf[n2], sBlo + boff + n2 * 16 * 80);
                // pass 1: Ahi * Blo
                #pragma unroll
                for (int mi = 0; mi < MI; mi++)
                    #pragma unroll
                    for (int ni = 0; ni < NI; ni++)
                        mma16816<F16>(acc[mi][ni], ahf[mi],
                                      blf[ni >> 1][(ni & 1) * 2],
                                      blf[ni >> 1][(ni & 1) * 2 + 1]);
                uint32_t alf[MI][4];
                #pragma unroll
                for (int mi = 0; mi < MI; mi++)
                    ldm_x4(alf[mi], sAlo + aoff + mi * 16 * 80);
                // pass 2: Alo * Bhi
                #pragma unroll
                for (int mi = 0; mi < MI; mi++)
                    #pragma unroll
                    for (int ni = 0; ni < NI; ni++)
                        mma16816<F16>(acc[mi][ni], alf[mi],
                                      bhf[ni >> 1][(ni & 1) * 2],
                                      bhf[ni >> 1][(ni & 1) * 2 + 1]);
            }
        }
    }

    // epilogue
    int r0 = (int)bm + wm * WM + (lane >> 2);
    int c0 = (int)bn + wn * WN + (lane & 3) * 2;
    #pragma unroll
    for (int mi = 0; mi < MI; mi++) {
        #pragma unroll
        for (int ni = 0; ni < NI; ni++) {
            int row = r0 + mi * 16;
            int col = c0 + ni * 8;
            float bx = 0.f, by = 0.f;
            if (bias) { bx = bias[col]; by = bias[col + 1]; }
            float2 lo, hi;
            lo.x = acc[mi][ni][0] + bx; lo.y = acc[mi][ni][1] + by;
            hi.x = acc[mi][ni][2] + bx; hi.y = acc[mi][ni][3] + by;
            *(float2*)(C + (size_t)row * N + col) = lo;
            *(float2*)(C + (size_t)(row + 8) * N + col) = hi;
        }
    }
}

// ---------------------------------------------------------------------------
// Embedding + positional encoding -> X fp32 and X2 bf16 split
// ---------------------------------------------------------------------------
__global__ __launch_bounds__(128) void embed_kernel(
    const int* __restrict__ ids, const float* __restrict__ emb,
    float* __restrict__ x, __nv_bfloat16* __restrict__ x2)
{
    int n = blockIdx.x;
    int s = n & (SS - 1);
    int id = ids[n];
    const float Cc = -0.01798894591761708f;  // -ln(10000)/512
    #pragma unroll
    for (int k = 0; k < 4; k++) {
        int d = threadIdx.x + k * 128;
        float ang = (float)s * expf((float)(d & ~1) * Cc);
        float pe = (d & 1) ? cosf(ang) : sinf(ang);
        float v = emb[(size_t)id * DD + d] + pe;
        x[(size_t)n * DD + d] = v;
        split2(v, &x2[(size_t)n * 2 * DD + d], &x2[(size_t)n * 2 * DD + DD + d]);
    }
}

// ---------------------------------------------------------------------------
// Windowed attention: 4 queries/block, warp-per-query.
// Score phase: 2 keys/iter, 16 lanes x 4 dims each. UNIFORM trip count for
// both half-warps (i0 loop) so the full-mask shuffles never diverge; the
// overshoot lane clamps its key index and discards the result.
// ---------------------------------------------------------------------------
__global__ __launch_bounds__(128) void attn_kernel(
    const float* __restrict__ qkv, __nv_bfloat16* __restrict__ out2)
{
    int s0 = blockIdx.x * 4, h = blockIdx.y, b = blockIdx.z;
    int win = (h + 1) * 64;
    int tid = threadIdx.x, lane = tid & 31, warp = tid >> 5;

    __shared__ float sc[4][512];
    __shared__ float inv_s[4];

    const float* base = qkv + (size_t)b * SS * (3 * DD);

    int sq = s0 + warp;
    int j0 = sq - win + 1; if (j0 < 0) j0 = 0;
    int cnt = sq + 1 - j0;

    int hl = lane >> 4;            // half-warp: key offset 0/1
    int l16 = lane & 15;           // dim group within half
    float4 qq4 = *(const float4*)(base + (size_t)sq * (3 * DD) + h * 64 + l16 * 4);

    float m = -3.4e38f;
    for (int i0 = 0; i0 < cnt; i0 += 2) {       // uniform across the warp
        int i = i0 + hl;
        int ic = i < cnt ? i : cnt - 1;         // clamp for overshoot lane
        const float4* kp = (const float4*)(base + (size_t)(j0 + ic) * (3 * DD) + DD + h * 64);
        float4 kk = kp[l16];
        float d = fmaf(kk.x, qq4.x, fmaf(kk.y, qq4.y,
                  fmaf(kk.z, qq4.z, kk.w * qq4.w)));
        #pragma unroll
        for (int o = 8; o; o >>= 1) d += __shfl_xor_sync(0xffffffffu, d, o);
        d *= 0.125f;                              // 1/sqrt(64)
        if (i < cnt) {
            if (l16 == 0) sc[warp][i] = d;
            m = fmaxf(m, d);
        }
    }
    // combine max across the two half-warps
    m = fmaxf(m, __shfl_xor_sync(0xffffffffu, m, 16));
    __syncwarp();

    float ssum = 0.f;
    for (int i = lane; i < cnt; i += 32) {
        float e = expf(sc[warp][i] - m);
        sc[warp][i] = e;
        ssum += e;
    }
    #pragma unroll
    for (int o = 16; o; o >>= 1) ssum += __shfl_xor_sync(0xffffffffu, ssum, o);
    if (lane == 0) inv_s[warp] = 1.0f / ssum;
    __syncthreads();

    // V pass: 64-thread group per query pair; d = tid&63
    int dcol = tid & 63;
    #pragma unroll
    for (int qi = (tid >> 6); qi < 4; qi += 2) {
        int sqq = s0 + qi;
        int jq0 = sqq - win + 1; if (jq0 < 0) jq0 = 0;
        int cq = sqq + 1 - jq0;
        const float* vb = base + (size_t)jq0 * (3 * DD) + 2 * DD + h * 64 + dcol;
        float a = 0.f;
        for (int i = 0; i < cq; i++)
            a += sc[qi][i] * vb[(size_t)i * (3 * DD)];
        float v = a * inv_s[qi];
        size_t n = (size_t)(b * SS + sqq);
        split2(v, &out2[n * 2 * DD + h * 64 + dcol],
                  &out2[n * 2 * DD + DD + h * 64 + dcol]);
    }
}

// ---------------------------------------------------------------------------
// (residual + split-K partial sum + bias) + LayerNorm.
// S>0: residual = sum_{s<S} part[s] + pbias (fixed order, deterministic).
// Optional fp32 / bf16-split / fp16 outputs.
// ---------------------------------------------------------------------------
template<int S>
__global__ __launch_bounds__(128) void ln_kernel(
    const float* __restrict__ xin, const float* __restrict__ part,
    const float* __restrict__ pbias,
    const float* __restrict__ g, const float* __restrict__ b,
    float* __restrict__ out, __nv_bfloat16* __restrict__ out2,
    __half* __restrict__ outh)
{
    int row = blockIdx.x;
    const float* xr = xin + (size_t)row * DD;
    int tid = threadIdx.x;
    float v[4];
    float s = 0.f, s2 = 0.f;
    #pragma unroll
    for (int k = 0; k < 4; k++) {
        int d = tid + k * 128;
        float t = xr[d];
        if (S > 0) {
            float r = pbias[d];
            #pragma unroll
            for (int ss = 0; ss < S; ss++)
                r += part[(size_t)ss * MNtok + (size_t)row * DD + d];
            t += r;
        }
        v[k] = t; s += t; s2 += t * t;
    }
    __shared__ float sh[2][4];
    #pragma unroll
    for (int o = 16; o; o >>= 1) {
        s  += __shfl_xor_sync(0xffffffffu, s, o);
        s2 += __shfl_xor_sync(0xffffffffu, s2, o);
    }
    if ((tid & 31) == 0) { sh[0][tid >> 5] = s; sh[1][tid >> 5] = s2; }
    __syncthreads();
    s  = sh[0][0] + sh[0][1] + sh[0][2] + sh[0][3];
    s2 = sh[1][0] + sh[1][1] + sh[1][2] + sh[1][3];
    float mean = s * (1.0f / 512.0f);
    float var = s2 * (1.0f / 512.0f) - mean * mean;
    float rstd = rsqrtf(var + 1e-5f);
    #pragma unroll
    for (int k = 0; k < 4; k++) {
        int d = tid + k * 128;
        float o = (v[k] - mean) * rstd * g[d] + b[d];
        if (out) out[(size_t)row * DD + d] = o;
        if (out2) split2(o, &out2[(size_t)row * 2 * DD + d],
                            &out2[(size_t)row * 2 * DD + DD + d]);
        if (outh) outh[(size_t)row * DD + d] = __float2half_rn(o);
    }
}

// ---------------------------------------------------------------------------
// SwiGLU -> bf16 split directly
// ---------------------------------------------------------------------------
__global__ __launch_bounds__(256) void swiglu_kernel(
    const float* __restrict__ h, __nv_bfloat16* __restrict__ ff2)
{
    int n = blockIdx.x;
    const float* hr = h + (size_t)n * (2 * FFN);
    __nv_bfloat16* fr = ff2 + (size_t)n * (2 * FFN);
    for (int f = threadIdx.x; f < FFN; f += 256) {
        float u = hr[f], gg = hr[FFN + f];
        float v = u * gg / (1.0f + expf(-gg));
        split2(v, &fr[f], &fr[FFN + f]);
    }
}

// ---------------------------------------------------------------------------
// Launch
// ---------------------------------------------------------------------------
#define SMEM_64_128_3 (3 * (2*64*80 + 2*128*80))   // 92160
#define SMEM_LM       (3 * (64*80 + 128*80))       // 46080

extern "C" void kernel_launch(void* const* d_in, const int* in_sizes, int n_in,
                              void* d_out, int out_size)
{
    const int*   ids   = (const int*)  d_in[0];
    const float* emb   = (const float*)d_in[1];
    const float* Wqkv  = (const float*)d_in[2];
    const float* bqkv  = (const float*)d_in[3];
    const float* Wo    = (const float*)d_in[4];
    const float* bo    = (const float*)d_in[5];
    const float* W1    = (const float*)d_in[6];
    const float* b1    = (const float*)d_in[7];
    const float* W2    = (const float*)d_in[8];
    const float* b2    = (const float*)d_in[9];
    const float* ln1_g = (const float*)d_in[10];
    const float* ln1_b = (const float*)d_in[11];
    const float* ln2_g = (const float*)d_in[12];
    const float* ln2_b = (const float*)d_in[13];
    const float* lnf_g = (const float*)d_in[14];
    const float* lnf_b = (const float*)d_in[15];
    float* out = (float*)d_out;

    float *X, *QKV, *HB, *PART;
    __nv_bfloat16 *wqkv2, *wo2, *w12, *w22, *x2, *att2, *ff2;
    __half *embh, *lnfh;
    cudaGetSymbolAddress((void**)&X,    g_X);
    cudaGetSymbolAddress((void**)&QKV,  g_QKV);
    cudaGetSymbolAddress((void**)&HB,   g_HB);
    cudaGetSymbolAddress((void**)&PART, g_PART);
    cudaGetSymbolAddress((void**)&wqkv2,g_wqkv2);
    cudaGetSymbolAddress((void**)&wo2,  g_wo2);
    cudaGetSymbolAddress((void**)&w12,  g_w12);
    cudaGetSymbolAddress((void**)&w22,  g_w22);
    cudaGetSymbolAddress((void**)&x2,   g_x2);
    cudaGetSymbolAddress((void**)&att2, g_att2);
    cudaGetSymbolAddress((void**)&ff2,  g_ff2);
    cudaGetSymbolAddress((void**)&embh, g_embh);
    cudaGetSymbolAddress((void**)&lnfh, g_lnfh);

    cudaFuncSetAttribute((const void*)gemm_mma<64,128,3,2>,
                         cudaFuncAttributeMaxDynamicSharedMemorySize, SMEM_64_128_3);
    cudaFuncSetAttribute((const void*)gemm_mma<64,128,1,2>,
                         cudaFuncAttributeMaxDynamicSharedMemorySize, SMEM_LM);

    // weight preprocessing (graph-replayed each call)
    prep_split<<<RQKV + RWO + RW1 + RW2, 256>>>(Wqkv, Wo, W1, W2,
                                                wqkv2, wo2, w12, w22);
    cvt_half_kernel<<<(VV * DD) / 1024, 256>>>(emb, embh, VV * DD);

    embed_kernel<<<NT, 128>>>(ids, emb, X, x2);

    const int MN = NT * DD;
    for (int l = 0; l < LL; l++) {
        // QKV: [2048,512] x [1536,512]^T   (64x128, 384 blocks, 2 CTA/SM)
        gemm_mma<64,128,3,2><<<dim3(12, 32), 256, SMEM_64_128_3>>>(
            x2, wqkv2 + (size_t)l * 3 * DD * 2 * DD,
            bqkv + (size_t)l * 3 * DD, QKV, 3 * DD, DD, DD, 0);
        // windowed attention -> att2 (bf16 split)
        attn_kernel<<<dim3(SS / 4, HH, BB), 128>>>(QKV, att2);
        // Wo: [2048,512] x [512,512]^T   split-K=2 -> 256 blocks
        gemm_mma<64,128,3,2><<<dim3(4, 32, 2), 256, SMEM_64_128_3>>>(
            att2, wo2 + (size_t)l * DD * 2 * DD,
            nullptr, PART, DD, DD, DD / 2, (size_t)MN);
        // x = LN(x + sum(partials) + bo)
        ln_kernel<2><<<NT, 128>>>(X, PART, bo + (size_t)l * DD,
                                  ln1_g + (size_t)l * DD, ln1_b + (size_t)l * DD,
                                  X, x2, nullptr);
        // W1: [2048,512] x [4096,512]^T   (64x128, 1024 blocks, 2 CTA/SM)
        gemm_mma<64,128,3,2><<<dim3(32, 32), 256, SMEM_64_128_3>>>(
            x2, w12 + (size_t)l * 2 * FFN * 2 * DD,
            b1 + (size_t)l * 2 * FFN, HB, 2 * FFN, DD, DD, 0);
        swiglu_kernel<<<NT, 256>>>(HB, ff2);
        // W2: [2048,2048] x [512,2048]^T  split-K=4 -> 512 blocks
        gemm_mma<64,128,3,2><<<dim3(4, 32, 4), 256, SMEM_64_128_3>>>(
            ff2, w22 + (size_t)l * DD * 2 * FFN,
            nullptr, PART, DD, FFN, FFN / 4, (size_t)MN);
        // x = LN(x + sum(partials) + b2)
        ln_kernel<4><<<NT, 128>>>(X, PART, b2 + (size_t)l * DD,
                                  ln2_g + (size_t)l * DD, ln2_b + (size_t)l * DD,
                                  X, x2, nullptr);
    }

    // final LN -> fp16, tied LM head (fp16, 64x128, 8000 blocks, 2 CTA/SM)
    ln_kernel<0><<<NT, 128>>>(X, nullptr, nullptr, lnf_g, lnf_b,
                              nullptr, nullptr, lnfh);
    gemm_mma<64,128,1,2><<<dim3(VV / 128, NT / 64), 256, SMEM_LM>>>(
        (const __nv_bfloat16*)lnfh, (const __nv_bfloat16*)embh,
        nullptr, out, VV, DD, DD, 0);
}

// round 11
// speedup vs baseline: 1.8740x; 1.0808x over previous
#include <cuda_runtime.h>
#include <cuda_bf16.h>
#include <cuda_fp16.h>
#include <stdint.h>
#include <math.h>

// Problem constants
#define BB 2
#define SS 1024
#define DD 512
#define HH 8
#define LL 6
#define VV 32000
#define FFN 2048
#define NT (BB*SS)          // 2048 tokens
#define MNtok (NT*DD)

// ---------------------------------------------------------------------------
// Device scratch (static, no allocations)
// ---------------------------------------------------------------------------
__device__ float g_X  [NT*DD];
__device__ float g_QKV[NT*3*DD];
__device__ float g_HB [NT*2*FFN];
__device__ float g_PART[4*NT*DD];                         // split-K partials

__device__ __nv_bfloat16 g_wqkv2[(size_t)LL*3*DD*2*DD];   // [rows, 2K] hi|lo
__device__ __nv_bfloat16 g_wo2  [(size_t)LL*DD*2*DD];
__device__ __nv_bfloat16 g_w12  [(size_t)LL*2*FFN*2*DD];
__device__ __nv_bfloat16 g_w22  [(size_t)LL*DD*2*FFN];
__device__ __nv_bfloat16 g_x2   [(size_t)NT*2*DD];
__device__ __nv_bfloat16 g_att2 [(size_t)NT*2*DD];
__device__ __nv_bfloat16 g_ff2  [(size_t)NT*2*FFN];
__device__ __half        g_embh [(size_t)VV*DD];          // fp16 for LM head
__device__ __half        g_lnfh [(size_t)NT*DD];

// ---------------------------------------------------------------------------
// PTX helpers (baseline ISA only: cp.async, ldmatrix, mma.sync)
// ---------------------------------------------------------------------------
__device__ __forceinline__ uint32_t smem_to_u32(const void* p) {
    uint32_t a;
    asm("{ .reg .u64 t; cvta.to.shared.u64 t, %1; cvt.u32.u64 %0, t; }"
        : "=r"(a) : "l"(p));
    return a;
}
__device__ __forceinline__ void cp16(uint32_t dst, const void* src) {
    asm volatile("cp.async.cg.shared.global [%0], [%1], 16;\n" :: "r"(dst), "l"(src) : "memory");
}
#define CP_COMMIT()  asm volatile("cp.async.commit_group;" ::: "memory")
#define CP_WAIT1()   asm volatile("cp.async.wait_group 1;" ::: "memory")

__device__ __forceinline__ void ldm_x4(uint32_t* r, uint32_t addr) {
    asm volatile("ldmatrix.sync.aligned.m8n8.x4.shared.b16 {%0,%1,%2,%3}, [%4];"
        : "=r"(r[0]), "=r"(r[1]), "=r"(r[2]), "=r"(r[3]) : "r"(addr));
}
template<bool F16>
__device__ __forceinline__ void mma16816(float* c, const uint32_t* a,
                                         uint32_t b0, uint32_t b1) {
    if (F16)
        asm volatile(
            "mma.sync.aligned.m16n8k16.row.col.f32.f16.f16.f32 "
            "{%0,%1,%2,%3}, {%4,%5,%6,%7}, {%8,%9}, {%0,%1,%2,%3};"
            : "+f"(c[0]), "+f"(c[1]), "+f"(c[2]), "+f"(c[3])
            : "r"(a[0]), "r"(a[1]), "r"(a[2]), "r"(a[3]), "r"(b0), "r"(b1));
    else
        asm volatile(
            "mma.sync.aligned.m16n8k16.row.col.f32.bf16.bf16.f32 "
            "{%0,%1,%2,%3}, {%4,%5,%6,%7}, {%8,%9}, {%0,%1,%2,%3};"
            : "+f"(c[0]), "+f"(c[1]), "+f"(c[2]), "+f"(c[3])
            : "r"(a[0]), "r"(a[1]), "r"(a[2]), "r"(a[3]), "r"(b0), "r"(b1));
}

// smem address for (row, chunk16) with 64B pitch + XOR swizzle.
// chunk' = chunk ^ ((row>>1)&3): conflict-free ldmatrix rows AND preserves
// phase under +16-row strides.
__device__ __forceinline__ uint32_t swz(int row, int chunk) {
    return (uint32_t)(row * 64 + ((chunk ^ ((row >> 1) & 3)) << 4));
}

// ---------------------------------------------------------------------------
// bf16 hi/lo split helpers
// ---------------------------------------------------------------------------
__device__ __forceinline__ void split2(float x, __nv_bfloat16* hi_p, __nv_bfloat16* lo_p) {
    __nv_bfloat16 h = __float2bfloat16_rn(x);
    *hi_p = h;
    *lo_p = __float2bfloat16_rn(x - __bfloat162float(h));
}

// Fused weight split: all 4 weight tensors in one launch.
#define RQKV (LL*3*DD)
#define RWO  (LL*DD)
#define RW1  (LL*2*FFN)
#define RW2  (LL*DD)
__global__ __launch_bounds__(256) void prep_split(
    const float* __restrict__ Wqkv, const float* __restrict__ Wo,
    const float* __restrict__ W1,   const float* __restrict__ W2,
    __nv_bfloat16* __restrict__ wqkv2, __nv_bfloat16* __restrict__ wo2,
    __nv_bfloat16* __restrict__ w12,   __nv_bfloat16* __restrict__ w22)
{
    int r = blockIdx.x;
    const float* s; __nv_bfloat16* d; int K;
    if (r < RQKV)                    { s = Wqkv + (size_t)r * DD; d = wqkv2 + (size_t)r * 2 * DD; K = DD; }
    else if (r < RQKV + RWO)         { r -= RQKV; s = Wo + (size_t)r * DD; d = wo2 + (size_t)r * 2 * DD; K = DD; }
    else if (r < RQKV + RWO + RW1)   { r -= RQKV + RWO; s = W1 + (size_t)r * DD; d = w12 + (size_t)r * 2 * DD; K = DD; }
    else                             { r -= RQKV + RWO + RW1; s = W2 + (size_t)r * FFN; d = w22 + (size_t)r * 2 * FFN; K = FFN; }
    for (int c = threadIdx.x; c < K; c += 256)
        split2(s[c], &d[c], &d[K + c]);
}

// fp32 -> fp16 plain convert
__global__ __launch_bounds__(256) void cvt_half_kernel(
    const float* __restrict__ s, __half* __restrict__ d, int n)
{
    int i = (blockIdx.x * 256 + threadIdx.x) * 4;
    if (i < n) {
        float4 v = *(const float4*)(s + i);
        d[i + 0] = __float2half_rn(v.x);
        d[i + 1] = __float2half_rn(v.y);
        d[i + 2] = __float2half_rn(v.z);
        d[i + 3] = __float2half_rn(v.w);
    }
}

// ---------------------------------------------------------------------------
// Tensor-core GEMM with optional split-K (blockIdx.z = split index).
// C[M,N] = A * B^T (+ bias when not split).
// PASSES=3 (bf16x3): A2,B2 = [rows, 2K] bf16 hi|lo; hi*hi + hi*lo + lo*hi.
// PASSES=1 (fp16):   A2,B2 = [rows, K] fp16, single pass.
// 256 threads (8 warps, 2m x 4n), warp tile (TM/2) x (TN/4), K-chunk 32,
// 3-buffer cp.async pipeline, lookahead 2.
// smem rows: 32 elems = 64B pitch + XOR swizzle (conflict-free ldmatrix).
// MINB=3 caps regs at ~85 for 3 CTAs/SM (smem 72KB/CTA).
// ---------------------------------------------------------------------------
template<int TM, int TN, int PASSES, int MINB>
__global__ __launch_bounds__(256, MINB)
void gemm_mma(const __nv_bfloat16* __restrict__ A2,
              const __nv_bfloat16* __restrict__ B2,
              const float* __restrict__ bias,
              float* __restrict__ C, int N, int K, int Ks, size_t partStride)
{
    constexpr bool F16 = (PASSES == 1);
    constexpr int WM = TM / 2, WN = TN / 4;
    constexpr int MI = WM / 16;
    constexpr int NI = WN / 8;
    constexpr int NB = WN / 16;
    constexpr int AT = (PASSES == 3) ? 2 : 1;
    constexpr int SA = AT * TM * 64;
    constexpr int SB = AT * TN * 64;
    constexpr int STAGE = SA + SB;
    constexpr int ACH = AT * TM * 4;
    constexpr int NCH = ACH + AT * TN * 4;

    extern __shared__ __align__(128) char dsm[];
    uint32_t sbase = smem_to_u32(dsm);

    int tid = threadIdx.x, lane = tid & 31, warp = tid >> 5;
    int wm = warp >> 2, wn = warp & 3;
    size_t bm = (size_t)blockIdx.y * TM;
    size_t bn = (size_t)blockIdx.x * TN;
    int kOff = blockIdx.z * Ks;
    C += (size_t)blockIdx.z * partStride;
    int astr = (PASSES == 3) ? 2 * K : K;
    int nk = Ks / 32;

    float acc[MI][NI][4];
    #pragma unroll
    for (int mi = 0; mi < MI; mi++)
        #pragma unroll
        for (int ni = 0; ni < NI; ni++)
            #pragma unroll
            for (int j = 0; j < 4; j++) acc[mi][ni][j] = 0.f;

    auto load_stage = [&](int it) {
        int buf = it % 3;
        int kc = kOff + it * 32;
        uint32_t sAp = sbase + buf * STAGE;
        uint32_t sBp = sAp + SA;
        #pragma unroll
        for (int ii = 0; ii < NCH / 256; ii++) {
            int i = tid + ii * 256;
            if (i < ACH) {
                int row, half, seg;
                if (PASSES == 3) { row = i >> 3; half = (i >> 2) & 1; seg = i & 3; }
                else             { row = i >> 2; half = 0;            seg = i & 3; }
                cp16(sAp + (uint32_t)(half * (TM * 64)) + swz(row, seg),
                     A2 + (bm + row) * (size_t)astr + half * K + kc + seg * 8);
            } else {
                int j = i - ACH;
                int row, half, seg;
                if (PASSES == 3) { row = j >> 3; half = (j >> 2) & 1; seg = j & 3; }
                else             { row = j >> 2; half = 0;            seg = j & 3; }
                cp16(sBp + (uint32_t)(half * (TN * 64)) + swz(row, seg),
                     B2 + (bn + row) * (size_t)astr + half * K + kc + seg * 8);
            }
        }
    };

    load_stage(0); CP_COMMIT();
    if (nk > 1) load_stage(1);
    CP_COMMIT();

    for (int it = 0; it < nk; it++) {
        CP_WAIT1();
        __syncthreads();
        if (it + 2 < nk) load_stage(it + 2);
        CP_COMMIT();

        int buf = it % 3;
        uint32_t sAhi = sbase + buf * STAGE;
        uint32_t sAlo = sAhi + TM * 64;
        uint32_t sBhi = sAhi + SA;
        uint32_t sBlo = sBhi + TN * 64;

        #pragma unroll
        for (int ks = 0; ks < 2; ks++) {
            int arow = wm * WM + (lane & 15);
            int achk = ks * 2 + (lane >> 4);
            uint32_t aoff = swz(arow, achk);           // +16-row strides keep phase
            int sel = lane >> 3, within = lane & 7;
            int nrow = wn * WN + within + ((sel >> 1) << 3);
            int bchk = ks * 2 + (sel & 1);
            uint32_t boff = swz(nrow, bchk);

            uint32_t ahf[MI][4], bhf[NB][4];
            #pragma unroll
            for (int mi = 0; mi < MI; mi++)
                ldm_x4(ahf[mi], sAhi + aoff + mi * 16 * 64);
            #pragma unroll
            for (int n2 = 0; n2 < NB; n2++)
                ldm_x4(bhf[n2], sBhi + boff + n2 * 16 * 64);

            // pass 0: hi * hi
            #pragma unroll
            for (int mi = 0; mi < MI; mi++)
                #pragma unroll
                for (int ni = 0; ni < NI; ni++)
                    mma16816<F16>(acc[mi][ni], ahf[mi],
                                  bhf[ni >> 1][(ni & 1) * 2],
                                  bhf[ni >> 1][(ni & 1) * 2 + 1]);
            if (PASSES == 3) {
                uint32_t blf[NB][4];
                #pragma unroll
                for (int n2 = 0; n2 < NB; n2++)
                    ldm_x4(blf[n2], sBlo + boff + n2 * 16 * 64);
                // pass 1: Ahi * Blo
                #pragma unroll
                for (int mi = 0; mi < MI; mi++)
                    #pragma unroll
                    for (int ni = 0; ni < NI; ni++)
                        mma16816<F16>(acc[mi][ni], ahf[mi],
                                      blf[ni >> 1][(ni & 1) * 2],
                                      blf[ni >> 1][(ni & 1) * 2 + 1]);
                uint32_t alf[MI][4];
                #pragma unroll
                for (int mi = 0; mi < MI; mi++)
                    ldm_x4(alf[mi], sAlo + aoff + mi * 16 * 64);
                // pass 2: Alo * Bhi
                #pragma unroll
                for (int mi = 0; mi < MI; mi++)
                    #pragma unroll
                    for (int ni = 0; ni < NI; ni++)
                        mma16816<F16>(acc[mi][ni], alf[mi],
                                      bhf[ni >> 1][(ni & 1) * 2],
                                      bhf[ni >> 1][(ni & 1) * 2 + 1]);
            }
        }
    }

    // epilogue
    int r0 = (int)bm + wm * WM + (lane >> 2);
    int c0 = (int)bn + wn * WN + (lane & 3) * 2;
    #pragma unroll
    for (int mi = 0; mi < MI; mi++) {
        #pragma unroll
        for (int ni = 0; ni < NI; ni++) {
            int row = r0 + mi * 16;
            int col = c0 + ni * 8;
            float bx = 0.f, by = 0.f;
            if (bias) { bx = bias[col]; by = bias[col + 1]; }
            float2 lo, hi;
            lo.x = acc[mi][ni][0] + bx; lo.y = acc[mi][ni][1] + by;
            hi.x = acc[mi][ni][2] + bx; hi.y = acc[mi][ni][3] + by;
            *(float2*)(C + (size_t)row * N + col) = lo;
            *(float2*)(C + (size_t)(row + 8) * N + col) = hi;
        }
    }
}

// ---------------------------------------------------------------------------
// Embedding + positional encoding -> X fp32 and X2 bf16 split
// ---------------------------------------------------------------------------
__global__ __launch_bounds__(128) void embed_kernel(
    const int* __restrict__ ids, const float* __restrict__ emb,
    float* __restrict__ x, __nv_bfloat16* __restrict__ x2)
{
    int n = blockIdx.x;
    int s = n & (SS - 1);
    int id = ids[n];
    const float Cc = -0.01798894591761708f;  // -ln(10000)/512
    #pragma unroll
    for (int k = 0; k < 4; k++) {
        int d = threadIdx.x + k * 128;
        float ang = (float)s * expf((float)(d & ~1) * Cc);
        float pe = (d & 1) ? cosf(ang) : sinf(ang);
        float v = emb[(size_t)id * DD + d] + pe;
        x[(size_t)n * DD + d] = v;
        split2(v, &x2[(size_t)n * 2 * DD + d], &x2[(size_t)n * 2 * DD + DD + d]);
    }
}

// ---------------------------------------------------------------------------
// Windowed attention: 4 queries/block, warp-per-query.
// Score phase: 2 keys/iter, 16 lanes x 4 dims each, uniform trip count.
// ---------------------------------------------------------------------------
__global__ __launch_bounds__(128) void attn_kernel(
    const float* __restrict__ qkv, __nv_bfloat16* __restrict__ out2)
{
    int s0 = blockIdx.x * 4, h = blockIdx.y, b = blockIdx.z;
    int win = (h + 1) * 64;
    int tid = threadIdx.x, lane = tid & 31, warp = tid >> 5;

    __shared__ float sc[4][512];
    __shared__ float inv_s[4];

    const float* base = qkv + (size_t)b * SS * (3 * DD);

    int sq = s0 + warp;
    int j0 = sq - win + 1; if (j0 < 0) j0 = 0;
    int cnt = sq + 1 - j0;

    int hl = lane >> 4;            // half-warp: key offset 0/1
    int l16 = lane & 15;           // dim group within half
    float4 qq4 = *(const float4*)(base + (size_t)sq * (3 * DD) + h * 64 + l16 * 4);

    float m = -3.4e38f;
    for (int i0 = 0; i0 < cnt; i0 += 2) {       // uniform across the warp
        int i = i0 + hl;
        int ic = i < cnt ? i : cnt - 1;         // clamp for overshoot lane
        const float4* kp = (const float4*)(base + (size_t)(j0 + ic) * (3 * DD) + DD + h * 64);
        float4 kk = kp[l16];
        float d = fmaf(kk.x, qq4.x, fmaf(kk.y, qq4.y,
                  fmaf(kk.z, qq4.z, kk.w * qq4.w)));
        #pragma unroll
        for (int o = 8; o; o >>= 1) d += __shfl_xor_sync(0xffffffffu, d, o);
        d *= 0.125f;                              // 1/sqrt(64)
        if (i < cnt) {
            if (l16 == 0) sc[warp][i] = d;
            m = fmaxf(m, d);
        }
    }
    m = fmaxf(m, __shfl_xor_sync(0xffffffffu, m, 16));
    __syncwarp();

    float ssum = 0.f;
    for (int i = lane; i < cnt; i += 32) {
        float e = expf(sc[warp][i] - m);
        sc[warp][i] = e;
        ssum += e;
    }
    #pragma unroll
    for (int o = 16; o; o >>= 1) ssum += __shfl_xor_sync(0xffffffffu, ssum, o);
    if (lane == 0) inv_s[warp] = 1.0f / ssum;
    __syncthreads();

    // V pass: 64-thread group per query pair; d = tid&63
    int dcol = tid & 63;
    #pragma unroll
    for (int qi = (tid >> 6); qi < 4; qi += 2) {
        int sqq = s0 + qi;
        int jq0 = sqq - win + 1; if (jq0 < 0) jq0 = 0;
        int cq = sqq + 1 - jq0;
        const float* vb = base + (size_t)jq0 * (3 * DD) + 2 * DD + h * 64 + dcol;
        float a = 0.f;
        for (int i = 0; i < cq; i++)
            a += sc[qi][i] * vb[(size_t)i * (3 * DD)];
        float v = a * inv_s[qi];
        size_t n = (size_t)(b * SS + sqq);
        split2(v, &out2[n * 2 * DD + h * 64 + dcol],
                  &out2[n * 2 * DD + DD + h * 64 + dcol]);
    }
}

// ---------------------------------------------------------------------------
// (residual + split-K partial sum + bias) + LayerNorm.
// S>0: residual = sum_{s<S} part[s] + pbias (fixed order, deterministic).
// Optional fp32 / bf16-split / fp16 outputs.
// ---------------------------------------------------------------------------
template<int S>
__global__ __launch_bounds__(128) void ln_kernel(
    const float* __restrict__ xin, const float* __restrict__ part,
    const float* __restrict__ pbias,
    const float* __restrict__ g, const float* __restrict__ b,
    float* __restrict__ out, __nv_bfloat16* __restrict__ out2,
    __half* __restrict__ outh)
{
    int row = blockIdx.x;
    const float* xr = xin + (size_t)row * DD;
    int tid = threadIdx.x;
    float v[4];
    float s = 0.f, s2 = 0.f;
    #pragma unroll
    for (int k = 0; k < 4; k++) {
        int d = tid + k * 128;
        float t = xr[d];
        if (S > 0) {
            float r = pbias[d];
            #pragma unroll
            for (int ss = 0; ss < S; ss++)
                r += part[(size_t)ss * MNtok + (size_t)row * DD + d];
            t += r;
        }
        v[k] = t; s += t; s2 += t * t;
    }
    __shared__ float sh[2][4];
    #pragma unroll
    for (int o = 16; o; o >>= 1) {
        s  += __shfl_xor_sync(0xffffffffu, s, o);
        s2 += __shfl_xor_sync(0xffffffffu, s2, o);
    }
    if ((tid & 31) == 0) { sh[0][tid >> 5] = s; sh[1][tid >> 5] = s2; }
    __syncthreads();
    s  = sh[0][0] + sh[0][1] + sh[0][2] + sh[0][3];
    s2 = sh[1][0] + sh[1][1] + sh[1][2] + sh[1][3];
    float mean = s * (1.0f / 512.0f);
    float var = s2 * (1.0f / 512.0f) - mean * mean;
    float rstd = rsqrtf(var + 1e-5f);
    #pragma unroll
    for (int k = 0; k < 4; k++) {
        int d = tid + k * 128;
        float o = (v[k] - mean) * rstd * g[d] + b[d];
        if (out) out[(size_t)row * DD + d] = o;
        if (out2) split2(o, &out2[(size_t)row * 2 * DD + d],
                            &out2[(size_t)row * 2 * DD + DD + d]);
        if (outh) outh[(size_t)row * DD + d] = __float2half_rn(o);
    }
}

// ---------------------------------------------------------------------------
// SwiGLU -> bf16 split directly
// ---------------------------------------------------------------------------
__global__ __launch_bounds__(256) void swiglu_kernel(
    const float* __restrict__ h, __nv_bfloat16* __restrict__ ff2)
{
    int n = blockIdx.x;
    const float* hr = h + (size_t)n * (2 * FFN);
    __nv_bfloat16* fr = ff2 + (size_t)n * (2 * FFN);
    for (int f = threadIdx.x; f < FFN; f += 256) {
        float u = hr[f], gg = hr[FFN + f];
        float v = u * gg / (1.0f + expf(-gg));
        split2(v, &fr[f], &fr[FFN + f]);
    }
}

// ---------------------------------------------------------------------------
// Launch
// ---------------------------------------------------------------------------
#define SMEM_64_128_3 (3 * (2*64*64 + 2*128*64))   // 73728
#define SMEM_LM       (3 * (64*64 + 128*64))       // 36864

extern "C" void kernel_launch(void* const* d_in, const int* in_sizes, int n_in,
                              void* d_out, int out_size)
{
    const int*   ids   = (const int*)  d_in[0];
    const float* emb   = (const float*)d_in[1];
    const float* Wqkv  = (const float*)d_in[2];
    const float* bqkv  = (const float*)d_in[3];
    const float* Wo    = (const float*)d_in[4];
    const float* bo    = (const float*)d_in[5];
    const float* W1    = (const float*)d_in[6];
    const float* b1    = (const float*)d_in[7];
    const float* W2    = (const float*)d_in[8];
    const float* b2    = (const float*)d_in[9];
    const float* ln1_g = (const float*)d_in[10];
    const float* ln1_b = (const float*)d_in[11];
    const float* ln2_g = (const float*)d_in[12];
    const float* ln2_b = (const float*)d_in[13];
    const float* lnf_g = (const float*)d_in[14];
    const float* lnf_b = (const float*)d_in[15];
    float* out = (float*)d_out;

    float *X, *QKV, *HB, *PART;
    __nv_bfloat16 *wqkv2, *wo2, *w12, *w22, *x2, *att2, *ff2;
    __half *embh, *lnfh;
    cudaGetSymbolAddress((void**)&X,    g_X);
    cudaGetSymbolAddress((void**)&QKV,  g_QKV);
    cudaGetSymbolAddress((void**)&HB,   g_HB);
    cudaGetSymbolAddress((void**)&PART, g_PART);
    cudaGetSymbolAddress((void**)&wqkv2,g_wqkv2);
    cudaGetSymbolAddress((void**)&wo2,  g_wo2);
    cudaGetSymbolAddress((void**)&w12,  g_w12);
    cudaGetSymbolAddress((void**)&w22,  g_w22);
    cudaGetSymbolAddress((void**)&x2,   g_x2);
    cudaGetSymbolAddress((void**)&att2, g_att2);
    cudaGetSymbolAddress((void**)&ff2,  g_ff2);
    cudaGetSymbolAddress((void**)&embh, g_embh);
    cudaGetSymbolAddress((void**)&lnfh, g_lnfh);

    cudaFuncSetAttribute((const void*)gemm_mma<64,128,3,3>,
                         cudaFuncAttributeMaxDynamicSharedMemorySize, SMEM_64_128_3);
    cudaFuncSetAttribute((const void*)gemm_mma<64,128,1,3>,
                         cudaFuncAttributeMaxDynamicSharedMemorySize, SMEM_LM);

    // weight preprocessing (graph-replayed each call)
    prep_split<<<RQKV + RWO + RW1 + RW2, 256>>>(Wqkv, Wo, W1, W2,
                                                wqkv2, wo2, w12, w22);
    cvt_half_kernel<<<(VV * DD) / 1024, 256>>>(emb, embh, VV * DD);

    embed_kernel<<<NT, 128>>>(ids, emb, X, x2);

    const int MN = NT * DD;
    for (int l = 0; l < LL; l++) {
        // QKV: [2048,512] x [1536,512]^T   (64x128, 384 blocks, 3 CTA/SM)
        gemm_mma<64,128,3,3><<<dim3(12, 32), 256, SMEM_64_128_3>>>(
            x2, wqkv2 + (size_t)l * 3 * DD * 2 * DD,
            bqkv + (size_t)l * 3 * DD, QKV, 3 * DD, DD, DD, 0);
        // windowed attention -> att2 (bf16 split)
        attn_kernel<<<dim3(SS / 4, HH, BB), 128>>>(QKV, att2);
        // Wo: [2048,512] x [512,512]^T   split-K=2 -> 256 blocks
        gemm_mma<64,128,3,3><<<dim3(4, 32, 2), 256, SMEM_64_128_3>>>(
            att2, wo2 + (size_t)l * DD * 2 * DD,
            nullptr, PART, DD, DD, DD / 2, (size_t)MN);
        // x = LN(x + sum(partials) + bo)
        ln_kernel<2><<<NT, 128>>>(X, PART, bo + (size_t)l * DD,
                                  ln1_g + (size_t)l * DD, ln1_b + (size_t)l * DD,
                                  X, x2, nullptr);
        // W1: [2048,512] x [4096,512]^T   (64x128, 1024 blocks)
        gemm_mma<64,128,3,3><<<dim3(32, 32), 256, SMEM_64_128_3>>>(
            x2, w12 + (size_t)l * 2 * FFN * 2 * DD,
            b1 + (size_t)l * 2 * FFN, HB, 2 * FFN, DD, DD, 0);
        swiglu_kernel<<<NT, 256>>>(HB, ff2);
        // W2: [2048,2048] x [512,2048]^T  split-K=4 -> 512 blocks
        gemm_mma<64,128,3,3><<<dim3(4, 32, 4), 256, SMEM_64_128_3>>>(
            ff2, w22 + (size_t)l * DD * 2 * FFN,
            nullptr, PART, DD, FFN, FFN / 4, (size_t)MN);
        // x = LN(x + sum(partials) + b2)
        ln_kernel<4><<<NT, 128>>>(X, PART, b2 + (size_t)l * DD,
                                  ln2_g + (size_t)l * DD, ln2_b + (size_t)l * DD,
                                  X, x2, nullptr);
    }

    // final LN -> fp16, tied LM head (fp16, 64x128, 8000 blocks, 3 CTA/SM)
    ln_kernel<0><<<NT, 128>>>(X, nullptr, nullptr, lnf_g, lnf_b,
                              nullptr, nullptr, lnfh);
    gemm_mma<64,128,1,3><<<dim3(VV / 128, NT / 64), 256, SMEM_LM>>>(
        (const __nv_bfloat16*)lnfh, (const __nv_bfloat16*)embh,
        nullptr, out, VV, DD, DD, 0);
}

// round 12
// speedup vs baseline: 2.1791x; 1.1628x over previous
#include <cuda_runtime.h>
#include <cuda_bf16.h>
#include <cuda_fp16.h>
#include <stdint.h>
#include <math.h>

// Problem constants
#define BB 2
#define SS 1024
#define DD 512
#define HH 8
#define LL 6
#define VV 32000
#define FFN 2048
#define NT (BB*SS)          // 2048 tokens
#define MNtok (NT*DD)

// ---------------------------------------------------------------------------
// Device scratch (static, no allocations)
// ---------------------------------------------------------------------------
__device__ float g_X  [NT*DD];
__device__ float g_QKV[NT*3*DD];
__device__ float g_HB [NT*2*FFN];
__device__ float g_PART[4*NT*DD];                         // split-K partials

__device__ __nv_bfloat16 g_wqkv2[(size_t)LL*3*DD*2*DD];   // [rows, 2K] hi|lo
__device__ __nv_bfloat16 g_wo2  [(size_t)LL*DD*2*DD];
__device__ __nv_bfloat16 g_w12  [(size_t)LL*2*FFN*2*DD];
__device__ __nv_bfloat16 g_w22  [(size_t)LL*DD*2*FFN];
__device__ __nv_bfloat16 g_x2   [(size_t)NT*2*DD];
__device__ __nv_bfloat16 g_att2 [(size_t)NT*2*DD];
__device__ __nv_bfloat16 g_ff2  [(size_t)NT*2*FFN];
__device__ __half        g_embh [(size_t)VV*DD];          // fp16 for LM head
__device__ __half        g_lnfh [(size_t)NT*DD];

// ---------------------------------------------------------------------------
// PTX helpers (baseline ISA only: cp.async, ldmatrix, mma.sync)
// ---------------------------------------------------------------------------
__device__ __forceinline__ uint32_t smem_to_u32(const void* p) {
    uint32_t a;
    asm("{ .reg .u64 t; cvta.to.shared.u64 t, %1; cvt.u32.u64 %0, t; }"
        : "=r"(a) : "l"(p));
    return a;
}
__device__ __forceinline__ void cp16(uint32_t dst, const void* src) {
    asm volatile("cp.async.cg.shared.global [%0], [%1], 16;\n" :: "r"(dst), "l"(src) : "memory");
}
#define CP_COMMIT()  asm volatile("cp.async.commit_group;" ::: "memory")
#define CP_WAIT1()   asm volatile("cp.async.wait_group 1;" ::: "memory")

__device__ __forceinline__ void ldm_x4(uint32_t* r, uint32_t addr) {
    asm volatile("ldmatrix.sync.aligned.m8n8.x4.shared.b16 {%0,%1,%2,%3}, [%4];"
        : "=r"(r[0]), "=r"(r[1]), "=r"(r[2]), "=r"(r[3]) : "r"(addr));
}
template<bool F16>
__device__ __forceinline__ void mma16816(float* c, const uint32_t* a,
                                         uint32_t b0, uint32_t b1) {
    if (F16)
        asm volatile(
            "mma.sync.aligned.m16n8k16.row.col.f32.f16.f16.f32 "
            "{%0,%1,%2,%3}, {%4,%5,%6,%7}, {%8,%9}, {%0,%1,%2,%3};"
            : "+f"(c[0]), "+f"(c[1]), "+f"(c[2]), "+f"(c[3])
            : "r"(a[0]), "r"(a[1]), "r"(a[2]), "r"(a[3]), "r"(b0), "r"(b1));
    else
        asm volatile(
            "mma.sync.aligned.m16n8k16.row.col.f32.bf16.bf16.f32 "
            "{%0,%1,%2,%3}, {%4,%5,%6,%7}, {%8,%9}, {%0,%1,%2,%3};"
            : "+f"(c[0]), "+f"(c[1]), "+f"(c[2]), "+f"(c[3])
            : "r"(a[0]), "r"(a[1]), "r"(a[2]), "r"(a[3]), "r"(b0), "r"(b1));
}

// smem address for (row, chunk16) with 64B pitch + XOR swizzle.
__device__ __forceinline__ uint32_t swz(int row, int chunk) {
    return (uint32_t)(row * 64 + ((chunk ^ ((row >> 1) & 3)) << 4));
}

// ---------------------------------------------------------------------------
// bf16 hi/lo split helpers
// ---------------------------------------------------------------------------
__device__ __forceinline__ void split2(float x, __nv_bfloat16* hi_p, __nv_bfloat16* lo_p) {
    __nv_bfloat16 h = __float2bfloat16_rn(x);
    *hi_p = h;
    *lo_p = __float2bfloat16_rn(x - __bfloat162float(h));
}

// Fused weight split: all 4 weight tensors in one launch.
#define RQKV (LL*3*DD)
#define RWO  (LL*DD)
#define RW1  (LL*2*FFN)
#define RW2  (LL*DD)
__global__ __launch_bounds__(256) void prep_split(
    const float* __restrict__ Wqkv, const float* __restrict__ Wo,
    const float* __restrict__ W1,   const float* __restrict__ W2,
    __nv_bfloat16* __restrict__ wqkv2, __nv_bfloat16* __restrict__ wo2,
    __nv_bfloat16* __restrict__ w12,   __nv_bfloat16* __restrict__ w22)
{
    int r = blockIdx.x;
    const float* s; __nv_bfloat16* d; int K;
    if (r < RQKV)                    { s = Wqkv + (size_t)r * DD; d = wqkv2 + (size_t)r * 2 * DD; K = DD; }
    else if (r < RQKV + RWO)         { r -= RQKV; s = Wo + (size_t)r * DD; d = wo2 + (size_t)r * 2 * DD; K = DD; }
    else if (r < RQKV + RWO + RW1)   { r -= RQKV + RWO; s = W1 + (size_t)r * DD; d = w12 + (size_t)r * 2 * DD; K = DD; }
    else                             { r -= RQKV + RWO + RW1; s = W2 + (size_t)r * FFN; d = w22 + (size_t)r * 2 * FFN; K = FFN; }
    for (int c = threadIdx.x; c < K; c += 256)
        split2(s[c], &d[c], &d[K + c]);
}

// fp32 -> fp16 plain convert
__global__ __launch_bounds__(256) void cvt_half_kernel(
    const float* __restrict__ s, __half* __restrict__ d, int n)
{
    int i = (blockIdx.x * 256 + threadIdx.x) * 4;
    if (i < n) {
        float4 v = *(const float4*)(s + i);
        d[i + 0] = __float2half_rn(v.x);
        d[i + 1] = __float2half_rn(v.y);
        d[i + 2] = __float2half_rn(v.z);
        d[i + 3] = __float2half_rn(v.w);
    }
}

// ---------------------------------------------------------------------------
// Tensor-core GEMM with optional split-K (blockIdx.z = split index).
// (unchanged from R11 — verified 35.4us / tensor 45% / 3 CTA/SM)
// ---------------------------------------------------------------------------
template<int TM, int TN, int PASSES, int MINB>
__global__ __launch_bounds__(256, MINB)
void gemm_mma(const __nv_bfloat16* __restrict__ A2,
              const __nv_bfloat16* __restrict__ B2,
              const float* __restrict__ bias,
              float* __restrict__ C, int N, int K, int Ks, size_t partStride)
{
    constexpr bool F16 = (PASSES == 1);
    constexpr int WM = TM / 2, WN = TN / 4;
    constexpr int MI = WM / 16;
    constexpr int NI = WN / 8;
    constexpr int NB = WN / 16;
    constexpr int AT = (PASSES == 3) ? 2 : 1;
    constexpr int SA = AT * TM * 64;
    constexpr int SB = AT * TN * 64;
    constexpr int STAGE = SA + SB;
    constexpr int ACH = AT * TM * 4;
    constexpr int NCH = ACH + AT * TN * 4;

    extern __shared__ __align__(128) char dsm[];
    uint32_t sbase = smem_to_u32(dsm);

    int tid = threadIdx.x, lane = tid & 31, warp = tid >> 5;
    int wm = warp >> 2, wn = warp & 3;
    size_t bm = (size_t)blockIdx.y * TM;
    size_t bn = (size_t)blockIdx.x * TN;
    int kOff = blockIdx.z * Ks;
    C += (size_t)blockIdx.z * partStride;
    int astr = (PASSES == 3) ? 2 * K : K;
    int nk = Ks / 32;

    float acc[MI][NI][4];
    #pragma unroll
    for (int mi = 0; mi < MI; mi++)
        #pragma unroll
        for (int ni = 0; ni < NI; ni++)
            #pragma unroll
            for (int j = 0; j < 4; j++) acc[mi][ni][j] = 0.f;

    auto load_stage = [&](int it) {
        int buf = it % 3;
        int kc = kOff + it * 32;
        uint32_t sAp = sbase + buf * STAGE;
        uint32_t sBp = sAp + SA;
        #pragma unroll
        for (int ii = 0; ii < NCH / 256; ii++) {
            int i = tid + ii * 256;
            if (i < ACH) {
                int row, half, seg;
                if (PASSES == 3) { row = i >> 3; half = (i >> 2) & 1; seg = i & 3; }
                else             { row = i >> 2; half = 0;            seg = i & 3; }
                cp16(sAp + (uint32_t)(half * (TM * 64)) + swz(row, seg),
                     A2 + (bm + row) * (size_t)astr + half * K + kc + seg * 8);
            } else {
                int j = i - ACH;
                int row, half, seg;
                if (PASSES == 3) { row = j >> 3; half = (j >> 2) & 1; seg = j & 3; }
                else             { row = j >> 2; half = 0;            seg = j & 3; }
                cp16(sBp + (uint32_t)(half * (TN * 64)) + swz(row, seg),
                     B2 + (bn + row) * (size_t)astr + half * K + kc + seg * 8);
            }
        }
    };

    load_stage(0); CP_COMMIT();
    if (nk > 1) load_stage(1);
    CP_COMMIT();

    for (int it = 0; it < nk; it++) {
        CP_WAIT1();
        __syncthreads();
        if (it + 2 < nk) load_stage(it + 2);
        CP_COMMIT();

        int buf = it % 3;
        uint32_t sAhi = sbase + buf * STAGE;
        uint32_t sAlo = sAhi + TM * 64;
        uint32_t sBhi = sAhi + SA;
        uint32_t sBlo = sBhi + TN * 64;

        #pragma unroll
        for (int ks = 0; ks < 2; ks++) {
            int arow = wm * WM + (lane & 15);
            int achk = ks * 2 + (lane >> 4);
            uint32_t aoff = swz(arow, achk);
            int sel = lane >> 3, within = lane & 7;
            int nrow = wn * WN + within + ((sel >> 1) << 3);
            int bchk = ks * 2 + (sel & 1);
            uint32_t boff = swz(nrow, bchk);

            uint32_t ahf[MI][4], bhf[NB][4];
            #pragma unroll
            for (int mi = 0; mi < MI; mi++)
                ldm_x4(ahf[mi], sAhi + aoff + mi * 16 * 64);
            #pragma unroll
            for (int n2 = 0; n2 < NB; n2++)
                ldm_x4(bhf[n2], sBhi + boff + n2 * 16 * 64);

            // pass 0: hi * hi
            #pragma unroll
            for (int mi = 0; mi < MI; mi++)
                #pragma unroll
                for (int ni = 0; ni < NI; ni++)
                    mma16816<F16>(acc[mi][ni], ahf[mi],
                                  bhf[ni >> 1][(ni & 1) * 2],
                                  bhf[ni >> 1][(ni & 1) * 2 + 1]);
            if (PASSES == 3) {
                uint32_t blf[NB][4];
                #pragma unroll
                for (int n2 = 0; n2 < NB; n2++)
                    ldm_x4(blf[n2], sBlo + boff + n2 * 16 * 64);
                // pass 1: Ahi * Blo
                #pragma unroll
                for (int mi = 0; mi < MI; mi++)
                    #pragma unroll
                    for (int ni = 0; ni < NI; ni++)
                        mma16816<F16>(acc[mi][ni], ahf[mi],
                                      blf[ni >> 1][(ni & 1) * 2],
                                      blf[ni >> 1][(ni & 1) * 2 + 1]);
                uint32_t alf[MI][4];
                #pragma unroll
                for (int mi = 0; mi < MI; mi++)
                    ldm_x4(alf[mi], sAlo + aoff + mi * 16 * 64);
                // pass 2: Alo * Bhi
                #pragma unroll
                for (int mi = 0; mi < MI; mi++)
                    #pragma unroll
                    for (int ni = 0; ni < NI; ni++)
                        mma16816<F16>(acc[mi][ni], alf[mi],
                                      bhf[ni >> 1][(ni & 1) * 2],
                                      bhf[ni >> 1][(ni & 1) * 2 + 1]);
            }
        }
    }

    // epilogue
    int r0 = (int)bm + wm * WM + (lane >> 2);
    int c0 = (int)bn + wn * WN + (lane & 3) * 2;
    #pragma unroll
    for (int mi = 0; mi < MI; mi++) {
        #pragma unroll
        for (int ni = 0; ni < NI; ni++) {
            int row = r0 + mi * 16;
            int col = c0 + ni * 8;
            float bx = 0.f, by = 0.f;
            if (bias) { bx = bias[col]; by = bias[col + 1]; }
            float2 lo, hi;
            lo.x = acc[mi][ni][0] + bx; lo.y = acc[mi][ni][1] + by;
            hi.x = acc[mi][ni][2] + bx; hi.y = acc[mi][ni][3] + by;
            *(float2*)(C + (size_t)row * N + col) = lo;
            *(float2*)(C + (size_t)(row + 8) * N + col) = hi;
        }
    }
}

// ---------------------------------------------------------------------------
// Embedding + positional encoding -> X fp32 and X2 bf16 split
// ---------------------------------------------------------------------------
__global__ __launch_bounds__(128) void embed_kernel(
    const int* __restrict__ ids, const float* __restrict__ emb,
    float* __restrict__ x, __nv_bfloat16* __restrict__ x2)
{
    int n = blockIdx.x;
    int s = n & (SS - 1);
    int id = ids[n];
    const float Cc = -0.01798894591761708f;  // -ln(10000)/512
    #pragma unroll
    for (int k = 0; k < 4; k++) {
        int d = threadIdx.x + k * 128;
        float ang = (float)s * expf((float)(d & ~1) * Cc);
        float pe = (d & 1) ? cosf(ang) : sinf(ang);
        float v = emb[(size_t)id * DD + d] + pe;
        x[(size_t)n * DD + d] = v;
        split2(v, &x2[(size_t)n * 2 * DD + d], &x2[(size_t)n * 2 * DD + DD + d]);
    }
}

// ---------------------------------------------------------------------------
// Windowed attention: 4 queries/block, warp-per-query.
// Score: 4 keys/iter, 8 lanes x 8 dims/key -> 3 shuffles per 4 keys
// (xor 1,2,4 within 8-lane subgroup; cross-subgroup max via xor 8,16 once).
// Uniform trip count; guarded writes (never divergent collectives).
// V: warp owns its query; lane owns 2 dims (float2); 4 independent
// accumulators break the FMA chain. No block-wide sync needed.
// ---------------------------------------------------------------------------
__global__ __launch_bounds__(128) void attn_kernel(
    const float* __restrict__ qkv, __nv_bfloat16* __restrict__ out2)
{
    int s0 = blockIdx.x * 4, h = blockIdx.y, b = blockIdx.z;
    int win = (h + 1) * 64;
    int tid = threadIdx.x, lane = tid & 31, warp = tid >> 5;

    __shared__ float sc[4][512];

    const float* base = qkv + (size_t)b * SS * (3 * DD);

    int sq = s0 + warp;
    int j0 = sq - win + 1; if (j0 < 0) j0 = 0;
    int cnt = sq + 1 - j0;

    int g = lane >> 3;             // key subgroup 0..3
    int l8 = lane & 7;             // dim octet within key
    const float4* qp = (const float4*)(base + (size_t)sq * (3 * DD) + h * 64 + l8 * 8);
    float4 qa = qp[0], qb = qp[1];

    float m = -3.4e38f;
    for (int i0 = 0; i0 < cnt; i0 += 4) {       // uniform across the warp
        int i = i0 + g;
        int ic = i < cnt ? i : cnt - 1;         // clamp overshoot subgroups
        const float4* kp = (const float4*)(base + (size_t)(j0 + ic) * (3 * DD) + DD + h * 64 + l8 * 8);
        float4 k0 = kp[0], k1 = kp[1];
        float d = fmaf(k0.x, qa.x, fmaf(k0.y, qa.y, fmaf(k0.z, qa.z, k0.w * qa.w)));
        d = fmaf(k1.x, qb.x, fmaf(k1.y, qb.y, fmaf(k1.z, qb.z, fmaf(k1.w, qb.w, d))));
        d += __shfl_xor_sync(0xffffffffu, d, 1);
        d += __shfl_xor_sync(0xffffffffu, d, 2);
        d += __shfl_xor_sync(0xffffffffu, d, 4);
        d *= 0.125f;                              // 1/sqrt(64)
        if (i < cnt) {
            if (l8 == 0) sc[warp][i] = d;
            m = fmaxf(m, d);
        }
    }
    // combine max across the four key subgroups
    m = fmaxf(m, __shfl_xor_sync(0xffffffffu, m, 8));
    m = fmaxf(m, __shfl_xor_sync(0xffffffffu, m, 16));
    __syncwarp();

    float ssum = 0.f;
    for (int i = lane; i < cnt; i += 32) {
        float e = expf(sc[warp][i] - m);
        sc[warp][i] = e;
        ssum += e;
    }
    #pragma unroll
    for (int o = 16; o; o >>= 1) ssum += __shfl_xor_sync(0xffffffffu, ssum, o);
    float inv = 1.0f / ssum;
    __syncwarp();

    // ---- V pass: lane owns dims {2*lane, 2*lane+1}, 4 independent accs ----
    const float* vb = base + (size_t)j0 * (3 * DD) + 2 * DD + h * 64 + lane * 2;
    float2 a0 = {0,0}, a1 = {0,0}, a2 = {0,0}, a3 = {0,0};
    int i = 0;
    for (; i + 4 <= cnt; i += 4) {
        float p0 = sc[warp][i + 0], p1 = sc[warp][i + 1];
        float p2 = sc[warp][i + 2], p3 = sc[warp][i + 3];
        float2 v0 = *(const float2*)(vb + (size_t)(i + 0) * (3 * DD));
        float2 v1 = *(const float2*)(vb + (size_t)(i + 1) * (3 * DD));
        float2 v2 = *(const float2*)(vb + (size_t)(i + 2) * (3 * DD));
        float2 v3 = *(const float2*)(vb + (size_t)(i + 3) * (3 * DD));
        a0.x = fmaf(p0, v0.x, a0.x); a0.y = fmaf(p0, v0.y, a0.y);
        a1.x = fmaf(p1, v1.x, a1.x); a1.y = fmaf(p1, v1.y, a1.y);
        a2.x = fmaf(p2, v2.x, a2.x); a2.y = fmaf(p2, v2.y, a2.y);
        a3.x = fmaf(p3, v3.x, a3.x); a3.y = fmaf(p3, v3.y, a3.y);
    }
    for (; i < cnt; i++) {
        float p = sc[warp][i];
        float2 v = *(const float2*)(vb + (size_t)i * (3 * DD));
        a0.x = fmaf(p, v.x, a0.x); a0.y = fmaf(p, v.y, a0.y);
    }
    float rx = (a0.x + a1.x) + (a2.x + a3.x);
    float ry = (a0.y + a1.y) + (a2.y + a3.y);

    size_t n = (size_t)(b * SS + sq);
    __nv_bfloat16* oh = out2 + n * 2 * DD + h * 64 + lane * 2;
    __nv_bfloat16* ol = oh + DD;
    split2(rx * inv, &oh[0], &ol[0]);
    split2(ry * inv, &oh[1], &ol[1]);
}

// ---------------------------------------------------------------------------
// (residual + split-K partial sum + bias) + LayerNorm.
// ---------------------------------------------------------------------------
template<int S>
__global__ __launch_bounds__(128) void ln_kernel(
    const float* __restrict__ xin, const float* __restrict__ part,
    const float* __restrict__ pbias,
    const float* __restrict__ g, const float* __restrict__ b,
    float* __restrict__ out, __nv_bfloat16* __restrict__ out2,
    __half* __restrict__ outh)
{
    int row = blockIdx.x;
    const float* xr = xin + (size_t)row * DD;
    int tid = threadIdx.x;
    float v[4];
    float s = 0.f, s2 = 0.f;
    #pragma unroll
    for (int k = 0; k < 4; k++) {
        int d = tid + k * 128;
        float t = xr[d];
        if (S > 0) {
            float r = pbias[d];
            #pragma unroll
            for (int ss = 0; ss < S; ss++)
                r += part[(size_t)ss * MNtok + (size_t)row * DD + d];
            t += r;
        }
        v[k] = t; s += t; s2 += t * t;
    }
    __shared__ float sh[2][4];
    #pragma unroll
    for (int o = 16; o; o >>= 1) {
        s  += __shfl_xor_sync(0xffffffffu, s, o);
        s2 += __shfl_xor_sync(0xffffffffu, s2, o);
    }
    if ((tid & 31) == 0) { sh[0][tid >> 5] = s; sh[1][tid >> 5] = s2; }
    __syncthreads();
    s  = sh[0][0] + sh[0][1] + sh[0][2] + sh[0][3];
    s2 = sh[1][0] + sh[1][1] + sh[1][2] + sh[1][3];
    float mean = s * (1.0f / 512.0f);
    float var = s2 * (1.0f / 512.0f) - mean * mean;
    float rstd = rsqrtf(var + 1e-5f);
    #pragma unroll
    for (int k = 0; k < 4; k++) {
        int d = tid + k * 128;
        float o = (v[k] - mean) * rstd * g[d] + b[d];
        if (out) out[(size_t)row * DD + d] = o;
        if (out2) split2(o, &out2[(size_t)row * 2 * DD + d],
                            &out2[(size_t)row * 2 * DD + DD + d]);
        if (outh) outh[(size_t)row * DD + d] = __float2half_rn(o);
    }
}

// ---------------------------------------------------------------------------
// SwiGLU -> bf16 split directly
// ---------------------------------------------------------------------------
__global__ __launch_bounds__(256) void swiglu_kernel(
    const float* __restrict__ h, __nv_bfloat16* __restrict__ ff2)
{
    int n = blockIdx.x;
    const float* hr = h + (size_t)n * (2 * FFN);
    __nv_bfloat16* fr = ff2 + (size_t)n * (2 * FFN);
    for (int f = threadIdx.x; f < FFN; f += 256) {
        float u = hr[f], gg = hr[FFN + f];
        float v = u * gg / (1.0f + expf(-gg));
        split2(v, &fr[f], &fr[FFN + f]);
    }
}

// ---------------------------------------------------------------------------
// Launch
// ---------------------------------------------------------------------------
#define SMEM_64_128_3 (3 * (2*64*64 + 2*128*64))   // 73728
#define SMEM_LM       (3 * (64*64 + 128*64))       // 36864

extern "C" void kernel_launch(void* const* d_in, const int* in_sizes, int n_in,
                              void* d_out, int out_size)
{
    const int*   ids   = (const int*)  d_in[0];
    const float* emb   = (const float*)d_in[1];
    const float* Wqkv  = (const float*)d_in[2];
    const float* bqkv  = (const float*)d_in[3];
    const float* Wo    = (const float*)d_in[4];
    const float* bo    = (const float*)d_in[5];
    const float* W1    = (const float*)d_in[6];
    const float* b1    = (const float*)d_in[7];
    const float* W2    = (const float*)d_in[8];
    const float* b2    = (const float*)d_in[9];
    const float* ln1_g = (const float*)d_in[10];
    const float* ln1_b = (const float*)d_in[11];
    const float* ln2_g = (const float*)d_in[12];
    const float* ln2_b = (const float*)d_in[13];
    const float* lnf_g = (const float*)d_in[14];
    const float* lnf_b = (const float*)d_in[15];
    float* out = (float*)d_out;

    float *X, *QKV, *HB, *PART;
    __nv_bfloat16 *wqkv2, *wo2, *w12, *w22, *x2, *att2, *ff2;
    __half *embh, *lnfh;
    cudaGetSymbolAddress((void**)&X,    g_X);
    cudaGetSymbolAddress((void**)&QKV,  g_QKV);
    cudaGetSymbolAddress((void**)&HB,   g_HB);
    cudaGetSymbolAddress((void**)&PART, g_PART);
    cudaGetSymbolAddress((void**)&wqkv2,g_wqkv2);
    cudaGetSymbolAddress((void**)&wo2,  g_wo2);
    cudaGetSymbolAddress((void**)&w12,  g_w12);
    cudaGetSymbolAddress((void**)&w22,  g_w22);
    cudaGetSymbolAddress((void**)&x2,   g_x2);
    cudaGetSymbolAddress((void**)&att2, g_att2);
    cudaGetSymbolAddress((void**)&ff2,  g_ff2);
    cudaGetSymbolAddress((void**)&embh, g_embh);
    cudaGetSymbolAddress((void**)&lnfh, g_lnfh);

    cudaFuncSetAttribute((const void*)gemm_mma<64,128,3,3>,
                         cudaFuncAttributeMaxDynamicSharedMemorySize, SMEM_64_128_3);
    cudaFuncSetAttribute((const void*)gemm_mma<64,128,1,3>,
                         cudaFuncAttributeMaxDynamicSharedMemorySize, SMEM_LM);

    // weight preprocessing (graph-replayed each call)
    prep_split<<<RQKV + RWO + RW1 + RW2, 256>>>(Wqkv, Wo, W1, W2,
                                                wqkv2, wo2, w12, w22);
    cvt_half_kernel<<<(VV * DD) / 1024, 256>>>(emb, embh, VV * DD);

    embed_kernel<<<NT, 128>>>(ids, emb, X, x2);

    const int MN = NT * DD;
    for (int l = 0; l < LL; l++) {
        // QKV: [2048,512] x [1536,512]^T   (64x128, 384 blocks, 3 CTA/SM)
        gemm_mma<64,128,3,3><<<dim3(12, 32), 256, SMEM_64_128_3>>>(
            x2, wqkv2 + (size_t)l * 3 * DD * 2 * DD,
            bqkv + (size_t)l * 3 * DD, QKV, 3 * DD, DD, DD, 0);
        // windowed attention -> att2 (bf16 split)
        attn_kernel<<<dim3(SS / 4, HH, BB), 128>>>(QKV, att2);
        // Wo: [2048,512] x [512,512]^T   split-K=2 -> 256 blocks
        gemm_mma<64,128,3,3><<<dim3(4, 32, 2), 256, SMEM_64_128_3>>>(
            att2, wo2 + (size_t)l * DD * 2 * DD,
            nullptr, PART, DD, DD, DD / 2, (size_t)MN);
        // x = LN(x + sum(partials) + bo)
        ln_kernel<2><<<NT, 128>>>(X, PART, bo + (size_t)l * DD,
                                  ln1_g + (size_t)l * DD, ln1_b + (size_t)l * DD,
                                  X, x2, nullptr);
        // W1: [2048,512] x [4096,512]^T   (64x128, 1024 blocks)
        gemm_mma<64,128,3,3><<<dim3(32, 32), 256, SMEM_64_128_3>>>(
            x2, w12 + (size_t)l * 2 * FFN * 2 * DD,
            b1 + (size_t)l * 2 * FFN, HB, 2 * FFN, DD, DD, 0);
        swiglu_kernel<<<NT, 256>>>(HB, ff2);
        // W2: [2048,2048] x [512,2048]^T  split-K=4 -> 512 blocks
        gemm_mma<64,128,3,3><<<dim3(4, 32, 4), 256, SMEM_64_128_3>>>(
            ff2, w22 + (size_t)l * DD * 2 * FFN,
            nullptr, PART, DD, FFN, FFN / 4, (size_t)MN);
        // x = LN(x + sum(partials) + b2)
        ln_kernel<4><<<NT, 128>>>(X, PART, b2 + (size_t)l * DD,
                                  ln2_g + (size_t)l * DD, ln2_b + (size_t)l * DD,
                                  X, x2, nullptr);
    }

    // final LN -> fp16, tied LM head (fp16, 64x128, 8000 blocks, 3 CTA/SM)
    ln_kernel<0><<<NT, 128>>>(X, nullptr, nullptr, lnf_g, lnf_b,
                              nullptr, nullptr, lnfh);
    gemm_mma<64,128,1,3><<<dim3(VV / 128, NT / 64), 256, SMEM_LM>>>(
        (const __nv_bfloat16*)lnfh, (const __nv_bfloat16*)embh,
        nullptr, out, VV, DD, DD, 0);
}

// round 13
// speedup vs baseline: 2.1930x; 1.0064x over previous
#include <cuda_runtime.h>
#include <cuda_bf16.h>
#include <cuda_fp16.h>
#include <stdint.h>
#include <math.h>

// Problem constants
#define BB 2
#define SS 1024
#define DD 512
#define HH 8
#define LL 6
#define VV 32000
#define FFN 2048
#define NT (BB*SS)          // 2048 tokens
#define MNtok (NT*DD)

// ---------------------------------------------------------------------------
// Device scratch (static, no allocations)
// ---------------------------------------------------------------------------
__device__ float g_X  [NT*DD];
__device__ float g_QKV[NT*3*DD];
__device__ float g_PART[4*NT*DD];                         // split-K partials

__device__ __nv_bfloat16 g_wqkv2[(size_t)LL*3*DD*2*DD];   // [rows, 2K] hi|lo
__device__ __nv_bfloat16 g_wo2  [(size_t)LL*DD*2*DD];
__device__ __nv_bfloat16 g_w12  [(size_t)LL*2*FFN*2*DD];  // u/g row-interleaved
__device__ __nv_bfloat16 g_w22  [(size_t)LL*DD*2*FFN];
__device__ __nv_bfloat16 g_x2   [(size_t)NT*2*DD];
__device__ __nv_bfloat16 g_att2 [(size_t)NT*2*DD];
__device__ __nv_bfloat16 g_ff2  [(size_t)NT*2*FFN];
__device__ __half        g_embh [(size_t)VV*DD];          // fp16 for LM head
__device__ __half        g_lnfh [(size_t)NT*DD];

// ---------------------------------------------------------------------------
// PTX helpers (baseline ISA only: cp.async, ldmatrix, mma.sync)
// ---------------------------------------------------------------------------
__device__ __forceinline__ uint32_t smem_to_u32(const void* p) {
    uint32_t a;
    asm("{ .reg .u64 t; cvta.to.shared.u64 t, %1; cvt.u32.u64 %0, t; }"
        : "=r"(a) : "l"(p));
    return a;
}
__device__ __forceinline__ void cp16(uint32_t dst, const void* src) {
    asm volatile("cp.async.cg.shared.global [%0], [%1], 16;\n" :: "r"(dst), "l"(src) : "memory");
}
#define CP_COMMIT()  asm volatile("cp.async.commit_group;" ::: "memory")
#define CP_WAIT1()   asm volatile("cp.async.wait_group 1;" ::: "memory")

__device__ __forceinline__ void ldm_x4(uint32_t* r, uint32_t addr) {
    asm volatile("ldmatrix.sync.aligned.m8n8.x4.shared.b16 {%0,%1,%2,%3}, [%4];"
        : "=r"(r[0]), "=r"(r[1]), "=r"(r[2]), "=r"(r[3]) : "r"(addr));
}
template<bool F16>
__device__ __forceinline__ void mma16816(float* c, const uint32_t* a,
                                         uint32_t b0, uint32_t b1) {
    if (F16)
        asm volatile(
            "mma.sync.aligned.m16n8k16.row.col.f32.f16.f16.f32 "
            "{%0,%1,%2,%3}, {%4,%5,%6,%7}, {%8,%9}, {%0,%1,%2,%3};"
            : "+f"(c[0]), "+f"(c[1]), "+f"(c[2]), "+f"(c[3])
            : "r"(a[0]), "r"(a[1]), "r"(a[2]), "r"(a[3]), "r"(b0), "r"(b1));
    else
        asm volatile(
            "mma.sync.aligned.m16n8k16.row.col.f32.bf16.bf16.f32 "
            "{%0,%1,%2,%3}, {%4,%5,%6,%7}, {%8,%9}, {%0,%1,%2,%3};"
            : "+f"(c[0]), "+f"(c[1]), "+f"(c[2]), "+f"(c[3])
            : "r"(a[0]), "r"(a[1]), "r"(a[2]), "r"(a[3]), "r"(b0), "r"(b1));
}

// smem address for (row, chunk16) with 64B pitch + XOR swizzle.
__device__ __forceinline__ uint32_t swz(int row, int chunk) {
    return (uint32_t)(row * 64 + ((chunk ^ ((row >> 1) & 3)) << 4));
}

// ---------------------------------------------------------------------------
// bf16 hi/lo split helpers
// ---------------------------------------------------------------------------
__device__ __forceinline__ void split2(float x, __nv_bfloat16* hi_p, __nv_bfloat16* lo_p) {
    __nv_bfloat16 h = __float2bfloat16_rn(x);
    *hi_p = h;
    *lo_p = __float2bfloat16_rn(x - __bfloat162float(h));
}

// Fused weight split. W1 is row-INTERLEAVED: dest row j (even) = u-row j/2,
// dest row j (odd) = g-row FFN + j/2 -> GEMM output cols (2f, 2f+1) = (u_f, g_f).
#define RQKV (LL*3*DD)
#define RWO  (LL*DD)
#define RW1  (LL*2*FFN)
#define RW2  (LL*DD)
__global__ __launch_bounds__(256) void prep_split(
    const float* __restrict__ Wqkv, const float* __restrict__ Wo,
    const float* __restrict__ W1,   const float* __restrict__ W2,
    __nv_bfloat16* __restrict__ wqkv2, __nv_bfloat16* __restrict__ wo2,
    __nv_bfloat16* __restrict__ w12,   __nv_bfloat16* __restrict__ w22)
{
    int r = blockIdx.x;
    const float* s; __nv_bfloat16* d; int K;
    if (r < RQKV)                    { s = Wqkv + (size_t)r * DD; d = wqkv2 + (size_t)r * 2 * DD; K = DD; }
    else if (r < RQKV + RWO)         { r -= RQKV; s = Wo + (size_t)r * DD; d = wo2 + (size_t)r * 2 * DD; K = DD; }
    else if (r < RQKV + RWO + RW1)   {
        r -= RQKV + RWO;
        int l = r / (2 * FFN), j = r % (2 * FFN);
        int srow = l * 2 * FFN + ((j & 1) ? FFN + (j >> 1) : (j >> 1));
        s = W1 + (size_t)srow * DD; d = w12 + (size_t)r * 2 * DD; K = DD;
    }
    else                             { r -= RQKV + RWO + RW1; s = W2 + (size_t)r * FFN; d = w22 + (size_t)r * 2 * FFN; K = FFN; }
    for (int c = threadIdx.x; c < K; c += 256)
        split2(s[c], &d[c], &d[K + c]);
}

// fp32 -> fp16 plain convert
__global__ __launch_bounds__(256) void cvt_half_kernel(
    const float* __restrict__ s, __half* __restrict__ d, int n)
{
    int i = (blockIdx.x * 256 + threadIdx.x) * 4;
    if (i < n) {
        float4 v = *(const float4*)(s + i);
        d[i + 0] = __float2half_rn(v.x);
        d[i + 1] = __float2half_rn(v.y);
        d[i + 2] = __float2half_rn(v.z);
        d[i + 3] = __float2half_rn(v.w);
    }
}

// ---------------------------------------------------------------------------
// Tensor-core GEMM with optional split-K (blockIdx.z = split index).
// EPI=0: C[M,N] = A*B^T (+bias / ->PART).
// EPI=1 (SwiGLU fusion, W1 only): weights row-interleaved so acc pairs are
// (u_f, g_f); epilogue computes u*silu(g) and writes bf16 hi/lo split to ff2.
// Mainloop unchanged (verified 34.7us / tensor 45% / 3 CTA/SM).
// ---------------------------------------------------------------------------
template<int TM, int TN, int PASSES, int MINB, int EPI>
__global__ __launch_bounds__(256, MINB)
void gemm_mma(const __nv_bfloat16* __restrict__ A2,
              const __nv_bfloat16* __restrict__ B2,
              const float* __restrict__ bias,
              float* __restrict__ C, int N, int K, int Ks, size_t partStride)
{
    constexpr bool F16 = (PASSES == 1);
    constexpr int WM = TM / 2, WN = TN / 4;
    constexpr int MI = WM / 16;
    constexpr int NI = WN / 8;
    constexpr int NB = WN / 16;
    constexpr int AT = (PASSES == 3) ? 2 : 1;
    constexpr int SA = AT * TM * 64;
    constexpr int SB = AT * TN * 64;
    constexpr int STAGE = SA + SB;
    constexpr int ACH = AT * TM * 4;
    constexpr int NCH = ACH + AT * TN * 4;

    extern __shared__ __align__(128) char dsm[];
    uint32_t sbase = smem_to_u32(dsm);

    int tid = threadIdx.x, lane = tid & 31, warp = tid >> 5;
    int wm = warp >> 2, wn = warp & 3;
    size_t bm = (size_t)blockIdx.y * TM;
    size_t bn = (size_t)blockIdx.x * TN;
    int kOff = blockIdx.z * Ks;
    C += (size_t)blockIdx.z * partStride;
    int astr = (PASSES == 3) ? 2 * K : K;
    int nk = Ks / 32;

    float acc[MI][NI][4];
    #pragma unroll
    for (int mi = 0; mi < MI; mi++)
        #pragma unroll
        for (int ni = 0; ni < NI; ni++)
            #pragma unroll
            for (int j = 0; j < 4; j++) acc[mi][ni][j] = 0.f;

    auto load_stage = [&](int it) {
        int buf = it % 3;
        int kc = kOff + it * 32;
        uint32_t sAp = sbase + buf * STAGE;
        uint32_t sBp = sAp + SA;
        #pragma unroll
        for (int ii = 0; ii < NCH / 256; ii++) {
            int i = tid + ii * 256;
            if (i < ACH) {
                int row, half, seg;
                if (PASSES == 3) { row = i >> 3; half = (i >> 2) & 1; seg = i & 3; }
                else             { row = i >> 2; half = 0;            seg = i & 3; }
                cp16(sAp + (uint32_t)(half * (TM * 64)) + swz(row, seg),
                     A2 + (bm + row) * (size_t)astr + half * K + kc + seg * 8);
            } else {
                int j = i - ACH;
                int row, half, seg;
                if (PASSES == 3) { row = j >> 3; half = (j >> 2) & 1; seg = j & 3; }
                else             { row = j >> 2; half = 0;            seg = j & 3; }
                cp16(sBp + (uint32_t)(half * (TN * 64)) + swz(row, seg),
                     B2 + (bn + row) * (size_t)astr + half * K + kc + seg * 8);
            }
        }
    };

    load_stage(0); CP_COMMIT();
    if (nk > 1) load_stage(1);
    CP_COMMIT();

    for (int it = 0; it < nk; it++) {
        CP_WAIT1();
        __syncthreads();
        if (it + 2 < nk) load_stage(it + 2);
        CP_COMMIT();

        int buf = it % 3;
        uint32_t sAhi = sbase + buf * STAGE;
        uint32_t sAlo = sAhi + TM * 64;
        uint32_t sBhi = sAhi + SA;
        uint32_t sBlo = sBhi + TN * 64;

        #pragma unroll
        for (int ks = 0; ks < 2; ks++) {
            int arow = wm * WM + (lane & 15);
            int achk = ks * 2 + (lane >> 4);
            uint32_t aoff = swz(arow, achk);
            int sel = lane >> 3, within = lane & 7;
            int nrow = wn * WN + within + ((sel >> 1) << 3);
            int bchk = ks * 2 + (sel & 1);
            uint32_t boff = swz(nrow, bchk);

            uint32_t ahf[MI][4], bhf[NB][4];
            #pragma unroll
            for (int mi = 0; mi < MI; mi++)
                ldm_x4(ahf[mi], sAhi + aoff + mi * 16 * 64);
            #pragma unroll
            for (int n2 = 0; n2 < NB; n2++)
                ldm_x4(bhf[n2], sBhi + boff + n2 * 16 * 64);

            // pass 0: hi * hi
            #pragma unroll
            for (int mi = 0; mi < MI; mi++)
                #pragma unroll
                for (int ni = 0; ni < NI; ni++)
                    mma16816<F16>(acc[mi][ni], ahf[mi],
                                  bhf[ni >> 1][(ni & 1) * 2],
                                  bhf[ni >> 1][(ni & 1) * 2 + 1]);
            if (PASSES == 3) {
                uint32_t blf[NB][4];
                #pragma unroll
                for (int n2 = 0; n2 < NB; n2++)
                    ldm_x4(blf[n2], sBlo + boff + n2 * 16 * 64);
                // pass 1: Ahi * Blo
                #pragma unroll
                for (int mi = 0; mi < MI; mi++)
                    #pragma unroll
                    for (int ni = 0; ni < NI; ni++)
                        mma16816<F16>(acc[mi][ni], ahf[mi],
                                      blf[ni >> 1][(ni & 1) * 2],
                                      blf[ni >> 1][(ni & 1) * 2 + 1]);
                uint32_t alf[MI][4];
                #pragma unroll
                for (int mi = 0; mi < MI; mi++)
                    ldm_x4(alf[mi], sAlo + aoff + mi * 16 * 64);
                // pass 2: Alo * Bhi
                #pragma unroll
                for (int mi = 0; mi < MI; mi++)
                    #pragma unroll
                    for (int ni = 0; ni < NI; ni++)
                        mma16816<F16>(acc[mi][ni], alf[mi],
                                      bhf[ni >> 1][(ni & 1) * 2],
                                      bhf[ni >> 1][(ni & 1) * 2 + 1]);
            }
        }
    }

    // epilogue
    int r0 = (int)bm + wm * WM + (lane >> 2);
    int c0 = (int)bn + wn * WN + (lane & 3) * 2;
    if (EPI == 1) {
        // SwiGLU fusion: cols (c, c+1) = (u_f, g_f), f = c/2. Output bf16
        // hi/lo split into ff2 [NT, 2*FFN].
        __nv_bfloat16* F = (__nv_bfloat16*)C;
        #pragma unroll
        for (int mi = 0; mi < MI; mi++) {
            #pragma unroll
            for (int ni = 0; ni < NI; ni++) {
                int row = r0 + mi * 16;
                int col = c0 + ni * 8;
                int f = col >> 1;
                float bu = bias[f], bg = bias[FFN + f];
                #pragma unroll
                for (int hrow = 0; hrow < 2; hrow++) {
                    int rr = row + hrow * 8;
                    float u = acc[mi][ni][hrow * 2 + 0] + bu;
                    float g = acc[mi][ni][hrow * 2 + 1] + bg;
                    float v = u * g / (1.0f + expf(-g));
                    split2(v, &F[(size_t)rr * (2 * FFN) + f],
                              &F[(size_t)rr * (2 * FFN) + FFN + f]);
                }
            }
        }
    } else {
        #pragma unroll
        for (int mi = 0; mi < MI; mi++) {
            #pragma unroll
            for (int ni = 0; ni < NI; ni++) {
                int row = r0 + mi * 16;
                int col = c0 + ni * 8;
                float bx = 0.f, by = 0.f;
                if (bias) { bx = bias[col]; by = bias[col + 1]; }
                float2 lo, hi;
                lo.x = acc[mi][ni][0] + bx; lo.y = acc[mi][ni][1] + by;
                hi.x = acc[mi][ni][2] + bx; hi.y = acc[mi][ni][3] + by;
                *(float2*)(C + (size_t)row * N + col) = lo;
                *(float2*)(C + (size_t)(row + 8) * N + col) = hi;
            }
        }
    }
}

// ---------------------------------------------------------------------------
// Embedding + positional encoding -> X fp32 and X2 bf16 split
// ---------------------------------------------------------------------------
__global__ __launch_bounds__(128) void embed_kernel(
    const int* __restrict__ ids, const float* __restrict__ emb,
    float* __restrict__ x, __nv_bfloat16* __restrict__ x2)
{
    int n = blockIdx.x;
    int s = n & (SS - 1);
    int id = ids[n];
    const float Cc = -0.01798894591761708f;  // -ln(10000)/512
    #pragma unroll
    for (int k = 0; k < 4; k++) {
        int d = threadIdx.x + k * 128;
        float ang = (float)s * expf((float)(d & ~1) * Cc);
        float pe = (d & 1) ? cosf(ang) : sinf(ang);
        float v = emb[(size_t)id * DD + d] + pe;
        x[(size_t)n * DD + d] = v;
        split2(v, &x2[(size_t)n * 2 * DD + d], &x2[(size_t)n * 2 * DD + DD + d]);
    }
}

// ---------------------------------------------------------------------------
// Windowed attention: 4 queries/block, warp-per-query (verified R12 version).
// ---------------------------------------------------------------------------
__global__ __launch_bounds__(128) void attn_kernel(
    const float* __restrict__ qkv, __nv_bfloat16* __restrict__ out2)
{
    int s0 = blockIdx.x * 4, h = blockIdx.y, b = blockIdx.z;
    int win = (h + 1) * 64;
    int tid = threadIdx.x, lane = tid & 31, warp = tid >> 5;

    __shared__ float sc[4][512];

    const float* base = qkv + (size_t)b * SS * (3 * DD);

    int sq = s0 + warp;
    int j0 = sq - win + 1; if (j0 < 0) j0 = 0;
    int cnt = sq + 1 - j0;

    int g = lane >> 3;             // key subgroup 0..3
    int l8 = lane & 7;             // dim octet within key
    const float4* qp = (const float4*)(base + (size_t)sq * (3 * DD) + h * 64 + l8 * 8);
    float4 qa = qp[0], qb = qp[1];

    float m = -3.4e38f;
    for (int i0 = 0; i0 < cnt; i0 += 4) {       // uniform across the warp
        int i = i0 + g;
        int ic = i < cnt ? i : cnt - 1;         // clamp overshoot subgroups
        const float4* kp = (const float4*)(base + (size_t)(j0 + ic) * (3 * DD) + DD + h * 64 + l8 * 8);
        float4 k0 = kp[0], k1 = kp[1];
        float d = fmaf(k0.x, qa.x, fmaf(k0.y, qa.y, fmaf(k0.z, qa.z, k0.w * qa.w)));
        d = fmaf(k1.x, qb.x, fmaf(k1.y, qb.y, fmaf(k1.z, qb.z, fmaf(k1.w, qb.w, d))));
        d += __shfl_xor_sync(0xffffffffu, d, 1);
        d += __shfl_xor_sync(0xffffffffu, d, 2);
        d += __shfl_xor_sync(0xffffffffu, d, 4);
        d *= 0.125f;                              // 1/sqrt(64)
        if (i < cnt) {
            if (l8 == 0) sc[warp][i] = d;
            m = fmaxf(m, d);
        }
    }
    m = fmaxf(m, __shfl_xor_sync(0xffffffffu, m, 8));
    m = fmaxf(m, __shfl_xor_sync(0xffffffffu, m, 16));
    __syncwarp();

    float ssum = 0.f;
    for (int i = lane; i < cnt; i += 32) {
        float e = expf(sc[warp][i] - m);
        sc[warp][i] = e;
        ssum += e;
    }
    #pragma unroll
    for (int o = 16; o; o >>= 1) ssum += __shfl_xor_sync(0xffffffffu, ssum, o);
    float inv = 1.0f / ssum;
    __syncwarp();

    // V pass: lane owns dims {2*lane, 2*lane+1}, 4 independent accs
    const float* vb = base + (size_t)j0 * (3 * DD) + 2 * DD + h * 64 + lane * 2;
    float2 a0 = {0,0}, a1 = {0,0}, a2 = {0,0}, a3 = {0,0};
    int i = 0;
    for (; i + 4 <= cnt; i += 4) {
        float p0 = sc[warp][i + 0], p1 = sc[warp][i + 1];
        float p2 = sc[warp][i + 2], p3 = sc[warp][i + 3];
        float2 v0 = *(const float2*)(vb + (size_t)(i + 0) * (3 * DD));
        float2 v1 = *(const float2*)(vb + (size_t)(i + 1) * (3 * DD));
        float2 v2 = *(const float2*)(vb + (size_t)(i + 2) * (3 * DD));
        float2 v3 = *(const float2*)(vb + (size_t)(i + 3) * (3 * DD));
        a0.x = fmaf(p0, v0.x, a0.x); a0.y = fmaf(p0, v0.y, a0.y);
        a1.x = fmaf(p1, v1.x, a1.x); a1.y = fmaf(p1, v1.y, a1.y);
        a2.x = fmaf(p2, v2.x, a2.x); a2.y = fmaf(p2, v2.y, a2.y);
        a3.x = fmaf(p3, v3.x, a3.x); a3.y = fmaf(p3, v3.y, a3.y);
    }
    for (; i < cnt; i++) {
        float p = sc[warp][i];
        float2 v = *(const float2*)(vb + (size_t)i * (3 * DD));
        a0.x = fmaf(p, v.x, a0.x); a0.y = fmaf(p, v.y, a0.y);
    }
    float rx = (a0.x + a1.x) + (a2.x + a3.x);
    float ry = (a0.y + a1.y) + (a2.y + a3.y);

    size_t n = (size_t)(b * SS + sq);
    __nv_bfloat16* oh = out2 + n * 2 * DD + h * 64 + lane * 2;
    __nv_bfloat16* ol = oh + DD;
    split2(rx * inv, &oh[0], &ol[0]);
    split2(ry * inv, &oh[1], &ol[1]);
}

// ---------------------------------------------------------------------------
// (residual + split-K partial sum + bias) + LayerNorm.
// ---------------------------------------------------------------------------
template<int S>
__global__ __launch_bounds__(128) void ln_kernel(
    const float* __restrict__ xin, const float* __restrict__ part,
    const float* __restrict__ pbias,
    const float* __restrict__ g, const float* __restrict__ b,
    float* __restrict__ out, __nv_bfloat16* __restrict__ out2,
    __half* __restrict__ outh)
{
    int row = blockIdx.x;
    const float* xr = xin + (size_t)row * DD;
    int tid = threadIdx.x;
    float v[4];
    float s = 0.f, s2 = 0.f;
    #pragma unroll
    for (int k = 0; k < 4; k++) {
        int d = tid + k * 128;
        float t = xr[d];
        if (S > 0) {
            float r = pbias[d];
            #pragma unroll
            for (int ss = 0; ss < S; ss++)
                r += part[(size_t)ss * MNtok + (size_t)row * DD + d];
            t += r;
        }
        v[k] = t; s += t; s2 += t * t;
    }
    __shared__ float sh[2][4];
    #pragma unroll
    for (int o = 16; o; o >>= 1) {
        s  += __shfl_xor_sync(0xffffffffu, s, o);
        s2 += __shfl_xor_sync(0xffffffffu, s2, o);
    }
    if ((tid & 31) == 0) { sh[0][tid >> 5] = s; sh[1][tid >> 5] = s2; }
    __syncthreads();
    s  = sh[0][0] + sh[0][1] + sh[0][2] + sh[0][3];
    s2 = sh[1][0] + sh[1][1] + sh[1][2] + sh[1][3];
    float mean = s * (1.0f / 512.0f);
    float var = s2 * (1.0f / 512.0f) - mean * mean;
    float rstd = rsqrtf(var + 1e-5f);
    #pragma unroll
    for (int k = 0; k < 4; k++) {
        int d = tid + k * 128;
        float o = (v[k] - mean) * rstd * g[d] + b[d];
        if (out) out[(size_t)row * DD + d] = o;
        if (out2) split2(o, &out2[(size_t)row * 2 * DD + d],
                            &out2[(size_t)row * 2 * DD + DD + d]);
        if (outh) outh[(size_t)row * DD + d] = __float2half_rn(o);
    }
}

// ---------------------------------------------------------------------------
// Launch
// ---------------------------------------------------------------------------
#define SMEM_64_128_3 (3 * (2*64*64 + 2*128*64))   // 73728
#define SMEM_LM       (3 * (64*64 + 128*64))       // 36864

extern "C" void kernel_launch(void* const* d_in, const int* in_sizes, int n_in,
                              void* d_out, int out_size)
{
    const int*   ids   = (const int*)  d_in[0];
    const float* emb   = (const float*)d_in[1];
    const float* Wqkv  = (const float*)d_in[2];
    const float* bqkv  = (const float*)d_in[3];
    const float* Wo    = (const float*)d_in[4];
    const float* bo    = (const float*)d_in[5];
    const float* W1    = (const float*)d_in[6];
    const float* b1    = (const float*)d_in[7];
    const float* W2    = (const float*)d_in[8];
    const float* b2    = (const float*)d_in[9];
    const float* ln1_g = (const float*)d_in[10];
    const float* ln1_b = (const float*)d_in[11];
    const float* ln2_g = (const float*)d_in[12];
    const float* ln2_b = (const float*)d_in[13];
    const float* lnf_g = (const float*)d_in[14];
    const float* lnf_b = (const float*)d_in[15];
    float* out = (float*)d_out;

    float *X, *QKV, *PART;
    __nv_bfloat16 *wqkv2, *wo2, *w12, *w22, *x2, *att2, *ff2;
    __half *embh, *lnfh;
    cudaGetSymbolAddress((void**)&X,    g_X);
    cudaGetSymbolAddress((void**)&QKV,  g_QKV);
    cudaGetSymbolAddress((void**)&PART, g_PART);
    cudaGetSymbolAddress((void**)&wqkv2,g_wqkv2);
    cudaGetSymbolAddress((void**)&wo2,  g_wo2);
    cudaGetSymbolAddress((void**)&w12,  g_w12);
    cudaGetSymbolAddress((void**)&w22,  g_w22);
    cudaGetSymbolAddress((void**)&x2,   g_x2);
    cudaGetSymbolAddress((void**)&att2, g_att2);
    cudaGetSymbolAddress((void**)&ff2,  g_ff2);
    cudaGetSymbolAddress((void**)&embh, g_embh);
    cudaGetSymbolAddress((void**)&lnfh, g_lnfh);

    cudaFuncSetAttribute((const void*)gemm_mma<64,128,3,3,0>,
                         cudaFuncAttributeMaxDynamicSharedMemorySize, SMEM_64_128_3);
    cudaFuncSetAttribute((const void*)gemm_mma<64,128,3,3,1>,
                         cudaFuncAttributeMaxDynamicSharedMemorySize, SMEM_64_128_3);
    cudaFuncSetAttribute((const void*)gemm_mma<64,128,1,3,0>,
                         cudaFuncAttributeMaxDynamicSharedMemorySize, SMEM_LM);

    // weight preprocessing (graph-replayed each call)
    prep_split<<<RQKV + RWO + RW1 + RW2, 256>>>(Wqkv, Wo, W1, W2,
                                                wqkv2, wo2, w12, w22);
    cvt_half_kernel<<<(VV * DD) / 1024, 256>>>(emb, embh, VV * DD);

    embed_kernel<<<NT, 128>>>(ids, emb, X, x2);

    const int MN = NT * DD;
    for (int l = 0; l < LL; l++) {
        // QKV: [2048,512] x [1536,512]^T   (64x128, 384 blocks, 3 CTA/SM)
        gemm_mma<64,128,3,3,0><<<dim3(12, 32), 256, SMEM_64_128_3>>>(
            x2, wqkv2 + (size_t)l * 3 * DD * 2 * DD,
            bqkv + (size_t)l * 3 * DD, QKV, 3 * DD, DD, DD, 0);
        // windowed attention -> att2 (bf16 split)
        attn_kernel<<<dim3(SS / 4, HH, BB), 128>>>(QKV, att2);
        // Wo: [2048,512] x [512,512]^T   split-K=2 -> 256 blocks
        gemm_mma<64,128,3,3,0><<<dim3(4, 32, 2), 256, SMEM_64_128_3>>>(
            att2, wo2 + (size_t)l * DD * 2 * DD,
            nullptr, PART, DD, DD, DD / 2, (size_t)MN);
        // x = LN(x + sum(partials) + bo)
        ln_kernel<2><<<NT, 128>>>(X, PART, bo + (size_t)l * DD,
                                  ln1_g + (size_t)l * DD, ln1_b + (size_t)l * DD,
                                  X, x2, nullptr);
        // W1 + fused SwiGLU: [2048,512] x [4096,512]^T -> ff2 bf16 split
        gemm_mma<64,128,3,3,1><<<dim3(32, 32), 256, SMEM_64_128_3>>>(
            x2, w12 + (size_t)l * 2 * FFN * 2 * DD,
            b1 + (size_t)l * 2 * FFN, (float*)ff2, 2 * FFN, DD, DD, 0);
        // W2: [2048,2048] x [512,2048]^T  split-K=4 -> 512 blocks
        gemm_mma<64,128,3,3,0><<<dim3(4, 32, 4), 256, SMEM_64_128_3>>>(
            ff2, w22 + (size_t)l * DD * 2 * FFN,
            nullptr, PART, DD, FFN, FFN / 4, (size_t)MN);
        // x = LN(x + sum(partials) + b2)
        ln_kernel<4><<<NT, 128>>>(X, PART, b2 + (size_t)l * DD,
                                  ln2_g + (size_t)l * DD, ln2_b + (size_t)l * DD,
                                  X, x2, nullptr);
    }

    // final LN -> fp16, tied LM head (fp16, 64x128, 8000 blocks, 3 CTA/SM)
    ln_kernel<0><<<NT, 128>>>(X, nullptr, nullptr, lnf_g, lnf_b,
                              nullptr, nullptr, lnfh);
    gemm_mma<64,128,1,3,0><<<dim3(VV / 128, NT / 64), 256, SMEM_LM>>>(
        (const __nv_bfloat16*)lnfh, (const __nv_bfloat16*)embh,
        nullptr, out, VV, DD, DD, 0);
}